// round 11
// baseline (speedup 1.0000x reference)
#include <cuda_runtime.h>
#include <math.h>

#define NBLK1 4096
#define LOG2E 1.44269504088896f

__device__ __align__(16) float g_ypre[4194304];   // (b,h,w,c)
__device__ float g_part[NBLK1 * 8];
__device__ float g_stats[32];

// shared-memory float offsets
#define OFF_WIN   0        // [32][128]
#define OFF_WX    4096     // [64][34]
#define OFF_WOUT  6272     // [64][32]
#define OFF_WDT   8320     // [2][64]
#define OFF_BDT2  8448     // [64]
#define OFF_DS2   8512     // [64]
#define OFF_XF    8576     // [32][33] = 1056
#define OFF_XP    9632     // [32][66]  (aliased by YS; per-thread read-before-write)
#define OFF_YS    9632
#define OFF_GZ    11744    // [32][64]
#define OFF_B     13792    // [32][16]
#define OFF_C     14304    // [32][16]
#define OFF_DTSR  14816    // [32][2]
#define OFF_GACC  14880    // [32][2]
#define SMEM_FLOATS 14944  // 59776 B -> smem allows 3 CTAs/SM

__device__ __forceinline__ float ex2f(float x) {
    float y; asm("ex2.approx.ftz.f32 %0, %1;" : "=f"(y) : "f"(x)); return y;
}
__device__ __forceinline__ float softplusf(float v) {
    float e = __expf(v);
    return (v < -3.0f) ? e * (1.0f - e * (0.5f - 0.33333334f * e)) : log1pf(e);
}
__device__ __forceinline__ float geluf(float v) {
    return 0.5f * v * (1.0f + erff(v * 0.70710678118f));
}

__global__ __launch_bounds__(256, 3) void k1_main(
    const float* __restrict__ x, const float* __restrict__ W_in,
    const float* __restrict__ W_x, const float* __restrict__ W_dt,
    const float* __restrict__ b_dt, const float* __restrict__ A_logs,
    const float* __restrict__ Ds, const float* __restrict__ W_out)
{
    extern __shared__ float S[];
    const int tid = threadIdx.x;
    const int bid = blockIdx.x;

    // ---------------- weights to smem ----------------
    for (int i = tid; i < 4096; i += 256) S[OFF_WIN + i] = W_in[i];
    for (int i = tid; i < 2176; i += 256) S[OFF_WX + i] = W_x[i];
    for (int i = tid; i < 2048; i += 256) S[OFF_WOUT + i] = W_out[i];
    if (tid < 128) S[OFF_WDT + tid] = W_dt[tid];
    if (tid < 64) {
        S[OFF_BDT2 + tid] = 2.0f * b_dt[tid];
        S[OFF_DS2 + tid]  = 2.0f * Ds[tid];
    }
    int ok = 1;
    for (int i = tid; i < 1024; i += 256) {
        int n = i & 15;
        float ae = __expf(A_logs[i]);
        if (fabsf(ae - (float)(n + 1)) > 1e-3f * (float)(n + 1)) ok = 0;
    }

    // ---------------- x tile (4 consecutive w positions) ----------------
    const int m0 = bid * 4;
    {
        int b = m0 >> 12;
        int h = (m0 >> 6) & 63;
        int w0 = m0 & 63;
        const float* xb = x + b * (256 * 4096) + h * 64 + w0;
        for (int i = tid; i < 1024; i += 256) {
            int c = i >> 2, p = i & 3;
            int t = c >> 5, g = c & 31;
            S[OFF_XF + (p * 8 + t) * 33 + g] = xb[c * 4096 + p];
        }
    }
    const int fast = __syncthreads_and(ok);

    // ---------------- GEMM1: [32x32]@[32x128] -> xp(0..63) | gelu(z)(64..127) -------
    {
        const int row = tid >> 3, cg = tid & 7;
        float acc[16];
        #pragma unroll
        for (int j = 0; j < 16; j++) acc[j] = 0.0f;
        const float4* W4 = reinterpret_cast<const float4*>(&S[OFF_WIN]);
        #pragma unroll 4
        for (int k = 0; k < 32; k++) {
            float a = S[OFF_XF + row * 33 + k];
            const float4* wr = W4 + k * 32 + cg * 4;
            #pragma unroll
            for (int q = 0; q < 4; q++) {
                float4 w = wr[q];
                acc[4*q+0] = fmaf(a, w.x, acc[4*q+0]);
                acc[4*q+1] = fmaf(a, w.y, acc[4*q+1]);
                acc[4*q+2] = fmaf(a, w.z, acc[4*q+2]);
                acc[4*q+3] = fmaf(a, w.w, acc[4*q+3]);
            }
        }
        if (cg < 4) {
            #pragma unroll
            for (int j = 0; j < 16; j++)
                S[OFF_XP + row * 66 + cg * 16 + j] = acc[j];
        } else {
            int c0 = (cg - 4) * 16;
            #pragma unroll
            for (int j = 0; j < 16; j++)
                S[OFF_GZ + row * 64 + c0 + j] = geluf(acc[j]);
        }
    }
    __syncthreads();

    // ---------------- GEMM2: [32x64]@[64x34] -> dts(0,1)|B(2..17)|C(18..33) ---------
    {
        const int rq = tid >> 3, cq = tid & 7;
        float acc[4];
        acc[0] = acc[1] = acc[2] = acc[3] = 0.0f;
        #pragma unroll 4
        for (int k = 0; k < 64; k++) {
            float a = S[OFF_XP + rq * 66 + k];
            const float* wp = &S[OFF_WX + k * 34 + 4 * cq];
            acc[0] = fmaf(a, wp[0], acc[0]);
            acc[1] = fmaf(a, wp[1], acc[1]);
            acc[2] = fmaf(a, wp[2], acc[2]);
            acc[3] = fmaf(a, wp[3], acc[3]);
        }
        #pragma unroll
        for (int j = 0; j < 4; j++) {
            int col = 4 * cq + j;
            if (col < 2)       S[OFF_DTSR + rq * 2 + col] = acc[j];
            else if (col < 18) S[OFF_B + rq * 16 + (col - 2)] = acc[j];
            else               S[OFF_C + rq * 16 + (col - 18)] = acc[j];
        }
        if (tid < 64) {
            // cols 32,33 -> C[14],C[15]
            int r = tid >> 1;
            int j = 32 + (tid & 1);
            float a2 = 0.0f;
            #pragma unroll
            for (int k = 0; k < 64; k++)
                a2 = fmaf(S[OFF_XP + r * 66 + k], S[OFF_WX + k * 34 + j], a2);
            S[OFF_C + r * 16 + (j - 18)] = a2;
        }
    }
    __syncthreads();

    // ------- bidirectional selective scan: 1 d-lane per thread -------
    // ALL loops fully unrolled: every du[t]/rra[t]/h[n] access statically indexed
    // (a single dynamic index anywhere would demote the arrays to local memory).
    {
        const int p = tid >> 6;     // position 0..3
        const int d = tid & 63;     // lane 0..63
        float du[8], rra[8];
        float h[16];
        #pragma unroll
        for (int n = 0; n < 16; n++) h[n] = 0.0f;

        if (fast) {
            // forward
            #pragma unroll
            for (int t = 0; t < 8; t++) {
                int r = p * 8 + t;
                float q0 = S[OFF_DTSR + r * 2];
                float q1 = S[OFF_DTSR + r * 2 + 1];
                float v = fmaf(q0, S[OFF_WDT + d], fmaf(q1, S[OFF_WDT + 64 + d], S[OFF_BDT2 + d]));
                float sp = softplusf(v);
                float u = S[OFF_XP + r * 66 + d];
                float rr = ex2f(-sp * LOG2E);
                du[t] = sp * u;
                rra[t] = rr;
                float a = rr, y = 0.0f;
                #pragma unroll
                for (int n = 0; n < 16; n++) {
                    float Bn = S[OFF_B + r * 16 + n];
                    float Cn = S[OFF_C + r * 16 + n];
                    h[n] = fmaf(a, h[n], du[t] * Bn);
                    y = fmaf(h[n], Cn, y);
                    if (n < 15) a *= rr;
                }
                S[OFF_YS + r * 66 + d] = fmaf(u, S[OFF_DS2 + d], y);
            }
            // backward + gate (latched du/rr only)
            #pragma unroll
            for (int n = 0; n < 16; n++) h[n] = 0.0f;
            #pragma unroll
            for (int t = 7; t >= 0; t--) {
                int r = p * 8 + t;
                float rr = rra[t];
                float a = rr, y = 0.0f;
                #pragma unroll
                for (int n = 0; n < 16; n++) {
                    float Bn = S[OFF_B + r * 16 + n];
                    float Cn = S[OFF_C + r * 16 + n];
                    h[n] = fmaf(a, h[n], du[t] * Bn);
                    y = fmaf(h[n], Cn, y);
                    if (n < 15) a *= rr;
                }
                S[OFF_YS + r * 66 + d] = (S[OFF_YS + r * 66 + d] + y) * S[OFF_GZ + r * 64 + d];
            }
        } else {
            // slow fallback: decays from gmem A_logs (rra holds softplus) — fully unrolled
            #pragma unroll
            for (int t = 0; t < 8; t++) {
                int r = p * 8 + t;
                float q0 = S[OFF_DTSR + r * 2];
                float q1 = S[OFF_DTSR + r * 2 + 1];
                float sp = softplusf(fmaf(q0, S[OFF_WDT + d], fmaf(q1, S[OFF_WDT + 64 + d], S[OFF_BDT2 + d])));
                float u = S[OFF_XP + r * 66 + d];
                du[t] = sp * u;
                rra[t] = sp;
                float y = 0.0f;
                #pragma unroll
                for (int n = 0; n < 16; n++) {
                    float Bn = S[OFF_B + r * 16 + n];
                    float Cn = S[OFF_C + r * 16 + n];
                    float a = __expf(-sp * __expf(__ldg(&A_logs[d * 16 + n])));
                    h[n] = fmaf(a, h[n], du[t] * Bn);
                    y = fmaf(h[n], Cn, y);
                }
                S[OFF_YS + r * 66 + d] = fmaf(u, S[OFF_DS2 + d], y);
            }
            #pragma unroll
            for (int n = 0; n < 16; n++) h[n] = 0.0f;
            #pragma unroll
            for (int t = 7; t >= 0; t--) {
                int r = p * 8 + t;
                float sp = rra[t];
                float y = 0.0f;
                #pragma unroll
                for (int n = 0; n < 16; n++) {
                    float Bn = S[OFF_B + r * 16 + n];
                    float Cn = S[OFF_C + r * 16 + n];
                    float a = __expf(-sp * __expf(__ldg(&A_logs[d * 16 + n])));
                    h[n] = fmaf(a, h[n], du[t] * Bn);
                    y = fmaf(h[n], Cn, y);
                }
                S[OFF_YS + r * 66 + d] = (S[OFF_YS + r * 66 + d] + y) * S[OFF_GZ + r * 64 + d];
            }
        }
    }
    __syncthreads();

    // ---------------- GEMM3: [32x64]@[64x32] -> y_pre + group partials ----------------
    {
        const int row = tid >> 3, cq = tid & 7;
        float acc[4];
        acc[0] = acc[1] = acc[2] = acc[3] = 0.0f;
        const float4* W4 = reinterpret_cast<const float4*>(&S[OFF_WOUT]);
        #pragma unroll 4
        for (int k = 0; k < 64; k++) {
            float a = S[OFF_YS + row * 66 + k];
            float4 w = W4[k * 8 + cq];
            acc[0] = fmaf(a, w.x, acc[0]);
            acc[1] = fmaf(a, w.y, acc[1]);
            acc[2] = fmaf(a, w.z, acc[2]);
            acc[3] = fmaf(a, w.w, acc[3]);
        }
        int p = row >> 3, t = row & 7;
        *reinterpret_cast<float4*>(&g_ypre[(m0 + p) * 256 + t * 32 + 4 * cq]) =
            make_float4(acc[0], acc[1], acc[2], acc[3]);
        float s  = acc[0] + acc[1] + acc[2] + acc[3];
        float ss = acc[0]*acc[0] + acc[1]*acc[1] + acc[2]*acc[2] + acc[3]*acc[3];
        #pragma unroll
        for (int off = 4; off; off >>= 1) {
            s  += __shfl_down_sync(0xffffffffu, s,  off, 8);
            ss += __shfl_down_sync(0xffffffffu, ss, off, 8);
        }
        if ((tid & 7) == 0) {
            S[OFF_GACC + row * 2]     = s;
            S[OFF_GACC + row * 2 + 1] = ss;
        }
    }
    __syncthreads();
    if (tid < 8) {
        int g = tid & 3, hh = tid >> 2;
        float v = 0.0f;
        #pragma unroll
        for (int q = 0; q < 4; q++) {
            v += S[OFF_GACC + (q * 8 + 2 * g) * 2 + hh];
            v += S[OFF_GACC + (q * 8 + 2 * g + 1) * 2 + hh];
        }
        g_part[bid * 8 + g * 2 + hh] = v;
    }
}

// ---------------- kernel 2: partials -> 16 stats ----------------
__global__ void k2_stats() {
    __shared__ float ssum[256], ssq[256];
    int b = blockIdx.x >> 2, g = blockIdx.x & 3;
    int tid = threadIdx.x;
    float s = 0.0f, q = 0.0f;
    for (int j = tid; j < 1024; j += 256) {
        int blk = b * 1024 + j;
        s += g_part[blk * 8 + g * 2];
        q += g_part[blk * 8 + g * 2 + 1];
    }
    ssum[tid] = s; ssq[tid] = q;
    __syncthreads();
    for (int st = 128; st; st >>= 1) {
        if (tid < st) { ssum[tid] += ssum[tid + st]; ssq[tid] += ssq[tid + st]; }
        __syncthreads();
    }
    if (tid == 0) {
        float invN = 1.0f / 262144.0f;
        float mean = ssum[0] * invN;
        float var  = ssq[0] * invN - mean * mean;
        g_stats[blockIdx.x * 2]     = mean;
        g_stats[blockIdx.x * 2 + 1] = rsqrtf(var + 1e-5f);
    }
}

// ---------------- kernel 3: groupnorm affine + transpose + residual ----------------
__global__ __launch_bounds__(256) void k3_final(
    const float* __restrict__ x, const float* __restrict__ gn_w,
    const float* __restrict__ gn_b, float* __restrict__ out)
{
    __shared__ float sm[32][33];
    int tx = threadIdx.x, ty = threadIdx.y;
    int ct = blockIdx.x & 7, wt = blockIdx.x >> 3;
    int h = blockIdx.y, b = blockIdx.z;
    int c0 = ct * 32, w0 = wt * 32;
    int c = c0 + tx;
    int grp = c >> 6;
    float mean = g_stats[(b * 4 + grp) * 2];
    float rsig = g_stats[(b * 4 + grp) * 2 + 1];
    float gw = gn_w[c], gb = gn_b[c];
    const float* yp = g_ypre + ((b * 64 + h) * 64 + w0) * 256;
    #pragma unroll
    for (int i = 0; i < 4; i++) {
        int wl = ty + 8 * i;
        float v = yp[wl * 256 + c];
        sm[wl][tx] = fmaf((v - mean) * rsig, gw, gb);
    }
    __syncthreads();
    #pragma unroll
    for (int i = 0; i < 4; i++) {
        int cl = ty + 8 * i;
        int gi = ((b * 256 + c0 + cl) * 64 + h) * 64 + w0 + tx;
        out[gi] = x[gi] + sm[tx][cl];
    }
}

extern "C" void kernel_launch(void* const* d_in, const int* in_sizes, int n_in,
                              void* d_out, int out_size) {
    const float* x      = (const float*)d_in[0];
    const float* W_in   = (const float*)d_in[1];
    const float* W_x    = (const float*)d_in[2];
    const float* W_dt   = (const float*)d_in[3];
    const float* b_dt   = (const float*)d_in[4];
    const float* A_logs = (const float*)d_in[5];
    const float* Ds     = (const float*)d_in[6];
    const float* W_out  = (const float*)d_in[7];
    const float* gn_w   = (const float*)d_in[8];
    const float* gn_b   = (const float*)d_in[9];
    float* out = (float*)d_out;

    cudaFuncSetAttribute(k1_main, cudaFuncAttributeMaxDynamicSharedMemorySize,
                         SMEM_FLOATS * 4);
    k1_main<<<NBLK1, 256, SMEM_FLOATS * 4>>>(x, W_in, W_x, W_dt, b_dt, A_logs, Ds, W_out);
    k2_stats<<<16, 256>>>();
    k3_final<<<dim3(16, 64, 4), dim3(32, 8)>>>(x, gn_w, gn_b, out);
}

// round 12
// speedup vs baseline: 1.9802x; 1.9802x over previous
#include <cuda_runtime.h>
#include <math.h>

#define NBLK1 2048
#define LOG2E 1.44269504088896f

__device__ __align__(16) float g_ypre[4194304];   // (b,h,w,c)
__device__ float g_part[NBLK1 * 8];
__device__ float g_stats[32];

// shared-memory float offsets (float4 arrays 16B-aligned)
#define OFF_WIN   0        // [32][128]
#define OFF_WX    4096     // [64][36]  (34 used; 4cq offsets 16B-aligned)
#define OFF_WOUT  6400     // [64][32]
#define OFF_WDT   8448     // [2][64]
#define OFF_BDT2  8576     // [64]
#define OFF_DS2   8640     // [64]
#define OFF_A2    8704     // [64][17]
#define OFF_XF    9792     // [64][33]
#define OFF_XP    11904    // [64][67]
#define OFF_GZ    16192    // [64][67]
#define OFF_YS    20480    // [64][67]
#define OFF_B     24768    // [64][16]
#define OFF_C     25792    // [64][16]
#define OFF_DTSR  26816    // [64][2]
#define OFF_GACC  26944    // [8][4][2]
#define SMEM_FLOATS 27008  // 108032 B -> 2 CTAs/SM

__device__ __forceinline__ float ex2f(float x) {
    float y; asm("ex2.approx.ftz.f32 %0, %1;" : "=f"(y) : "f"(x)); return y;
}

__global__ __launch_bounds__(256, 2) void k1_main(
    const float* __restrict__ x, const float* __restrict__ W_in,
    const float* __restrict__ W_x, const float* __restrict__ W_dt,
    const float* __restrict__ b_dt, const float* __restrict__ A_logs,
    const float* __restrict__ Ds, const float* __restrict__ W_out)
{
    extern __shared__ float S[];
    const int tid = threadIdx.x;
    const int bid = blockIdx.x;

    // ---------------- load weights to smem ----------------
    for (int i = tid; i < 4096; i += 256) S[OFF_WIN + i] = W_in[i];
    for (int i = tid; i < 64 * 34; i += 256) {
        int d = i / 34, j = i - d * 34;
        S[OFF_WX + d * 36 + j] = W_x[i];
    }
    for (int i = tid; i < 2048; i += 256) {
        int d = i >> 5, g = i & 31;
        S[OFF_WOUT + d * 32 + g] = W_out[i];
    }
    if (tid < 128) S[OFF_WDT + tid] = W_dt[tid];
    if (tid < 64) {
        S[OFF_BDT2 + tid] = 2.0f * b_dt[tid];
        S[OFF_DS2 + tid]  = 2.0f * Ds[tid];
    }
    int ok = 1;
    for (int i = tid; i < 1024; i += 256) {
        int d = i >> 4, n = i & 15;
        float ae = __expf(A_logs[i]);
        if (fabsf(ae - (float)(n + 1)) > 1e-3f * (float)(n + 1)) ok = 0;
        S[OFF_A2 + d * 17 + n] = -ae * LOG2E;
    }

    // ---------------- load x tile (8 consecutive w positions) ----------------
    {
        int m0 = bid * 8;
        int b = m0 >> 12;
        int h = (m0 >> 6) & 63;
        int w0 = m0 & 63;
        const float* xb = x + b * (256 * 4096) + h * 64 + w0;
        for (int i = tid; i < 2048; i += 256) {
            int c = i >> 3, p = i & 7;
            int t = c >> 5, g = c & 31;
            S[OFF_XF + (p * 8 + t) * 33 + g] = xb[c * 4096 + p];
        }
    }
    const int fast = __syncthreads_and(ok);

    // ---------------- GEMM1: [64x32]@[32x128] -> xp(0..63), gelu(z)(64..127) --------
    {
        int rp = tid >> 3;
        int cg = tid & 7;
        float acc[2][16];
        #pragma unroll
        for (int i = 0; i < 2; i++)
            #pragma unroll
            for (int j = 0; j < 16; j++) acc[i][j] = 0.0f;
        const float4* W4 = reinterpret_cast<const float4*>(&S[OFF_WIN]);
        #pragma unroll 4
        for (int k = 0; k < 32; k++) {
            float a0 = S[OFF_XF + (2 * rp) * 33 + k];
            float a1 = S[OFF_XF + (2 * rp + 1) * 33 + k];
            #pragma unroll
            for (int q = 0; q < 4; q++) {
                float4 w = W4[k * 32 + cg * 4 + q];
                acc[0][4*q+0] = fmaf(a0, w.x, acc[0][4*q+0]);
                acc[0][4*q+1] = fmaf(a0, w.y, acc[0][4*q+1]);
                acc[0][4*q+2] = fmaf(a0, w.z, acc[0][4*q+2]);
                acc[0][4*q+3] = fmaf(a0, w.w, acc[0][4*q+3]);
                acc[1][4*q+0] = fmaf(a1, w.x, acc[1][4*q+0]);
                acc[1][4*q+1] = fmaf(a1, w.y, acc[1][4*q+1]);
                acc[1][4*q+2] = fmaf(a1, w.z, acc[1][4*q+2]);
                acc[1][4*q+3] = fmaf(a1, w.w, acc[1][4*q+3]);
            }
        }
        #pragma unroll
        for (int i = 0; i < 2; i++) {
            int row = 2 * rp + i;
            #pragma unroll
            for (int j = 0; j < 16; j++) {
                int col = cg * 16 + j;
                float v = acc[i][j];
                if (col < 64) {
                    S[OFF_XP + row * 67 + col] = v;
                } else {
                    float ge = 0.5f * v * (1.0f + erff(v * 0.70710678118f));
                    S[OFF_GZ + row * 67 + (col - 64)] = ge;
                }
            }
        }
    }
    __syncthreads();

    // ---------------- GEMM2: [64x64]@[64x34] -> dts(0,1)|B(2..17)|C(18..33) ---------
    if (tid < 128) {
        int rq = tid >> 3;
        int cq = tid & 7;
        float acc[4][4];
        #pragma unroll
        for (int i = 0; i < 4; i++)
            #pragma unroll
            for (int j = 0; j < 4; j++) acc[i][j] = 0.0f;
        #pragma unroll 4
        for (int k = 0; k < 64; k++) {
            float a0 = S[OFF_XP + (4 * rq + 0) * 67 + k];
            float a1 = S[OFF_XP + (4 * rq + 1) * 67 + k];
            float a2 = S[OFF_XP + (4 * rq + 2) * 67 + k];
            float a3 = S[OFF_XP + (4 * rq + 3) * 67 + k];
            float4 w = *reinterpret_cast<const float4*>(&S[OFF_WX + k * 36 + 4 * cq]);
            acc[0][0]=fmaf(a0,w.x,acc[0][0]); acc[0][1]=fmaf(a0,w.y,acc[0][1]); acc[0][2]=fmaf(a0,w.z,acc[0][2]); acc[0][3]=fmaf(a0,w.w,acc[0][3]);
            acc[1][0]=fmaf(a1,w.x,acc[1][0]); acc[1][1]=fmaf(a1,w.y,acc[1][1]); acc[1][2]=fmaf(a1,w.z,acc[1][2]); acc[1][3]=fmaf(a1,w.w,acc[1][3]);
            acc[2][0]=fmaf(a2,w.x,acc[2][0]); acc[2][1]=fmaf(a2,w.y,acc[2][1]); acc[2][2]=fmaf(a2,w.z,acc[2][2]); acc[2][3]=fmaf(a2,w.w,acc[2][3]);
            acc[3][0]=fmaf(a3,w.x,acc[3][0]); acc[3][1]=fmaf(a3,w.y,acc[3][1]); acc[3][2]=fmaf(a3,w.z,acc[3][2]); acc[3][3]=fmaf(a3,w.w,acc[3][3]);
        }
        #pragma unroll
        for (int i = 0; i < 4; i++) {
            int r = 4 * rq + i;
            #pragma unroll
            for (int j = 0; j < 4; j++) {
                int col = 4 * cq + j;
                float v = acc[i][j];
                if (col < 2)       S[OFF_DTSR + r * 2 + col] = v;
                else if (col < 18) S[OFF_B + r * 16 + (col - 2)] = v;
                else               S[OFF_C + r * 16 + (col - 18)] = v;
            }
        }
    } else if (tid < 192) {
        // cols 32,33 -> C[14],C[15]
        int r = tid - 128;
        float c14 = 0.0f, c15 = 0.0f;
        #pragma unroll 8
        for (int k = 0; k < 64; k++) {
            float a = S[OFF_XP + r * 67 + k];
            c14 = fmaf(a, S[OFF_WX + k * 36 + 32], c14);
            c15 = fmaf(a, S[OFF_WX + k * 36 + 33], c15);
        }
        S[OFF_C + r * 16 + 14] = c14;
        S[OFF_C + r * 16 + 15] = c15;
    }
    __syncthreads();

    // ---------------- bidirectional selective scan ----------------
    {
        int p  = tid >> 5;
        int d0 = tid & 31;
        float du0[8], du1[8], dl0[8], dl1[8], rr0[8], rr1[8];
        #pragma unroll
        for (int t = 0; t < 8; t++) {
            int r = p * 8 + t;
            float q0 = S[OFF_DTSR + r * 2];
            float q1 = S[OFF_DTSR + r * 2 + 1];
            float v0 = fmaf(q0, S[OFF_WDT + d0],      fmaf(q1, S[OFF_WDT + 64 + d0],      S[OFF_BDT2 + d0]));
            float v1 = fmaf(q0, S[OFF_WDT + d0 + 32], fmaf(q1, S[OFF_WDT + 96 + d0],      S[OFF_BDT2 + d0 + 32]));
            float e0 = __expf(v0), e1 = __expf(v1);
            float s0 = (v0 < -3.0f) ? e0 * (1.0f - e0 * (0.5f - 0.33333334f * e0)) : log1pf(e0);
            float s1 = (v1 < -3.0f) ? e1 * (1.0f - e1 * (0.5f - 0.33333334f * e1)) : log1pf(e1);
            dl0[t] = s0; dl1[t] = s1;
            du0[t] = s0 * S[OFF_XP + r * 67 + d0];
            du1[t] = s1 * S[OFF_XP + r * 67 + d0 + 32];
            rr0[t] = ex2f(-s0 * LOG2E);
            rr1[t] = ex2f(-s1 * LOG2E);
        }
        const float* A2a = &S[OFF_A2 + d0 * 17];
        const float* A2b = &S[OFF_A2 + (d0 + 32) * 17];
        float h0[16], h1[16];
        #pragma unroll
        for (int n = 0; n < 16; n++) { h0[n] = 0.0f; h1[n] = 0.0f; }

        // forward pass
        for (int t = 0; t < 8; t++) {
            int r = p * 8 + t;
            float y0 = 0.0f, y1 = 0.0f;
            if (fast) {
                float a0 = rr0[t], a1 = rr1[t];
                const float4* Bp4 = reinterpret_cast<const float4*>(&S[OFF_B + r * 16]);
                const float4* Cp4 = reinterpret_cast<const float4*>(&S[OFF_C + r * 16]);
                #pragma unroll
                for (int jj = 0; jj < 4; jj++) {
                    float4 Bq = Bp4[jj];
                    float4 Cq = Cp4[jj];
                    int n = 4 * jj;
                    h0[n]   = fmaf(a0, h0[n],   du0[t] * Bq.x);  h1[n]   = fmaf(a1, h1[n],   du1[t] * Bq.x);
                    y0 = fmaf(h0[n],   Cq.x, y0);  y1 = fmaf(h1[n],   Cq.x, y1);  a0 *= rr0[t]; a1 *= rr1[t];
                    h0[n+1] = fmaf(a0, h0[n+1], du0[t] * Bq.y);  h1[n+1] = fmaf(a1, h1[n+1], du1[t] * Bq.y);
                    y0 = fmaf(h0[n+1], Cq.y, y0);  y1 = fmaf(h1[n+1], Cq.y, y1);  a0 *= rr0[t]; a1 *= rr1[t];
                    h0[n+2] = fmaf(a0, h0[n+2], du0[t] * Bq.z);  h1[n+2] = fmaf(a1, h1[n+2], du1[t] * Bq.z);
                    y0 = fmaf(h0[n+2], Cq.z, y0);  y1 = fmaf(h1[n+2], Cq.z, y1);  a0 *= rr0[t]; a1 *= rr1[t];
                    h0[n+3] = fmaf(a0, h0[n+3], du0[t] * Bq.w);  h1[n+3] = fmaf(a1, h1[n+3], du1[t] * Bq.w);
                    y0 = fmaf(h0[n+3], Cq.w, y0);  y1 = fmaf(h1[n+3], Cq.w, y1);
                    if (jj < 3) { a0 *= rr0[t]; a1 *= rr1[t]; }
                }
            } else {
                #pragma unroll
                for (int n = 0; n < 16; n++) {
                    float Bn = S[OFF_B + r * 16 + n];
                    float Cn = S[OFF_C + r * 16 + n];
                    float a0 = ex2f(dl0[t] * A2a[n]);
                    float a1 = ex2f(dl1[t] * A2b[n]);
                    h0[n] = fmaf(a0, h0[n], du0[t] * Bn);
                    h1[n] = fmaf(a1, h1[n], du1[t] * Bn);
                    y0 = fmaf(h0[n], Cn, y0);
                    y1 = fmaf(h1[n], Cn, y1);
                }
            }
            float u0 = S[OFF_XP + r * 67 + d0];
            float u1 = S[OFF_XP + r * 67 + d0 + 32];
            S[OFF_YS + r * 67 + d0]      = fmaf(u0, S[OFF_DS2 + d0], y0);
            S[OFF_YS + r * 67 + d0 + 32] = fmaf(u1, S[OFF_DS2 + d0 + 32], y1);
        }

        // backward pass + gate
        #pragma unroll
        for (int n = 0; n < 16; n++) { h0[n] = 0.0f; h1[n] = 0.0f; }
        for (int t = 7; t >= 0; t--) {
            int r = p * 8 + t;
            float y0 = 0.0f, y1 = 0.0f;
            if (fast) {
                float a0 = rr0[t], a1 = rr1[t];
                const float4* Bp4 = reinterpret_cast<const float4*>(&S[OFF_B + r * 16]);
                const float4* Cp4 = reinterpret_cast<const float4*>(&S[OFF_C + r * 16]);
                #pragma unroll
                for (int jj = 0; jj < 4; jj++) {
                    float4 Bq = Bp4[jj];
                    float4 Cq = Cp4[jj];
                    int n = 4 * jj;
                    h0[n]   = fmaf(a0, h0[n],   du0[t] * Bq.x);  h1[n]   = fmaf(a1, h1[n],   du1[t] * Bq.x);
                    y0 = fmaf(h0[n],   Cq.x, y0);  y1 = fmaf(h1[n],   Cq.x, y1);  a0 *= rr0[t]; a1 *= rr1[t];
                    h0[n+1] = fmaf(a0, h0[n+1], du0[t] * Bq.y);  h1[n+1] = fmaf(a1, h1[n+1], du1[t] * Bq.y);
                    y0 = fmaf(h0[n+1], Cq.y, y0);  y1 = fmaf(h1[n+1], Cq.y, y1);  a0 *= rr0[t]; a1 *= rr1[t];
                    h0[n+2] = fmaf(a0, h0[n+2], du0[t] * Bq.z);  h1[n+2] = fmaf(a1, h1[n+2], du1[t] * Bq.z);
                    y0 = fmaf(h0[n+2], Cq.z, y0);  y1 = fmaf(h1[n+2], Cq.z, y1);  a0 *= rr0[t]; a1 *= rr1[t];
                    h0[n+3] = fmaf(a0, h0[n+3], du0[t] * Bq.w);  h1[n+3] = fmaf(a1, h1[n+3], du1[t] * Bq.w);
                    y0 = fmaf(h0[n+3], Cq.w, y0);  y1 = fmaf(h1[n+3], Cq.w, y1);
                    if (jj < 3) { a0 *= rr0[t]; a1 *= rr1[t]; }
                }
            } else {
                #pragma unroll
                for (int n = 0; n < 16; n++) {
                    float Bn = S[OFF_B + r * 16 + n];
                    float Cn = S[OFF_C + r * 16 + n];
                    float a0 = ex2f(dl0[t] * A2a[n]);
                    float a1 = ex2f(dl1[t] * A2b[n]);
                    h0[n] = fmaf(a0, h0[n], du0[t] * Bn);
                    h1[n] = fmaf(a1, h1[n], du1[t] * Bn);
                    y0 = fmaf(h0[n], Cn, y0);
                    y1 = fmaf(h1[n], Cn, y1);
                }
            }
            S[OFF_YS + r * 67 + d0]      = (S[OFF_YS + r * 67 + d0]      + y0) * S[OFF_GZ + r * 67 + d0];
            S[OFF_YS + r * 67 + d0 + 32] = (S[OFF_YS + r * 67 + d0 + 32] + y1) * S[OFF_GZ + r * 67 + d0 + 32];
        }
    }
    __syncthreads();

    // ---------------- GEMM3: [64x64]@[64x32] -> y_pre + group partials ----------------
    {
        int rp = tid >> 3;
        int cq = tid & 7;
        float acc[2][4];
        #pragma unroll
        for (int i = 0; i < 2; i++)
            #pragma unroll
            for (int j = 0; j < 4; j++) acc[i][j] = 0.0f;
        const float4* W4o = reinterpret_cast<const float4*>(&S[OFF_WOUT]);
        #pragma unroll 4
        for (int k = 0; k < 64; k++) {
            float a0 = S[OFF_YS + (2 * rp) * 67 + k];
            float a1 = S[OFF_YS + (2 * rp + 1) * 67 + k];
            float4 w = W4o[k * 8 + cq];
            acc[0][0]=fmaf(a0,w.x,acc[0][0]); acc[0][1]=fmaf(a0,w.y,acc[0][1]);
            acc[0][2]=fmaf(a0,w.z,acc[0][2]); acc[0][3]=fmaf(a0,w.w,acc[0][3]);
            acc[1][0]=fmaf(a1,w.x,acc[1][0]); acc[1][1]=fmaf(a1,w.y,acc[1][1]);
            acc[1][2]=fmaf(a1,w.z,acc[1][2]); acc[1][3]=fmaf(a1,w.w,acc[1][3]);
        }
        int m0 = bid * 8;
        float s = 0.0f, ss = 0.0f;
        #pragma unroll
        for (int i = 0; i < 2; i++) {
            int row = 2 * rp + i;
            int p = row >> 3, t = row & 7;
            float4 v4 = make_float4(acc[i][0], acc[i][1], acc[i][2], acc[i][3]);
            *reinterpret_cast<float4*>(&g_ypre[(m0 + p) * 256 + t * 32 + 4 * cq]) = v4;
            s  += acc[i][0] + acc[i][1] + acc[i][2] + acc[i][3];
            ss += acc[i][0]*acc[i][0] + acc[i][1]*acc[i][1] + acc[i][2]*acc[i][2] + acc[i][3]*acc[i][3];
        }
        #pragma unroll
        for (int off = 4; off; off >>= 1) {
            s  += __shfl_down_sync(0xffffffffu, s,  off, 8);
            ss += __shfl_down_sync(0xffffffffu, ss, off, 8);
        }
        if ((tid & 7) == 0) {
            int w = tid >> 5, g = rp & 3;
            S[OFF_GACC + (w * 4 + g) * 2]     = s;
            S[OFF_GACC + (w * 4 + g) * 2 + 1] = ss;
        }
    }
    __syncthreads();
    if (tid < 8) {
        int g = tid & 3, hh = tid >> 2;
        float v = 0.0f;
        #pragma unroll
        for (int w = 0; w < 8; w++) v += S[OFF_GACC + (w * 4 + g) * 2 + hh];
        g_part[bid * 8 + g * 2 + hh] = v;
    }
}

// ---------------- kernel 2: partials -> 16 stats ----------------
__global__ void k2_stats() {
    __shared__ float ssum[256], ssq[256];
    int b = blockIdx.x >> 2, g = blockIdx.x & 3;
    int tid = threadIdx.x;
    float s = 0.0f, q = 0.0f;
    for (int j = tid; j < 512; j += 256) {
        int blk = b * 512 + j;
        s += g_part[blk * 8 + g * 2];
        q += g_part[blk * 8 + g * 2 + 1];
    }
    ssum[tid] = s; ssq[tid] = q;
    __syncthreads();
    for (int st = 128; st; st >>= 1) {
        if (tid < st) { ssum[tid] += ssum[tid + st]; ssq[tid] += ssq[tid + st]; }
        __syncthreads();
    }
    if (tid == 0) {
        float invN = 1.0f / 262144.0f;
        float mean = ssum[0] * invN;
        float var  = ssq[0] * invN - mean * mean;
        g_stats[blockIdx.x * 2]     = mean;
        g_stats[blockIdx.x * 2 + 1] = rsqrtf(var + 1e-5f);
    }
}

// ---------------- kernel 3: groupnorm affine + transpose + residual ----------------
__global__ __launch_bounds__(256) void k3_final(
    const float* __restrict__ x, const float* __restrict__ gn_w,
    const float* __restrict__ gn_b, float* __restrict__ out)
{
    __shared__ float sm[32][33];
    int tx = threadIdx.x, ty = threadIdx.y;
    int ct = blockIdx.x & 7, wt = blockIdx.x >> 3;
    int h = blockIdx.y, b = blockIdx.z;
    int c0 = ct * 32, w0 = wt * 32;
    int c = c0 + tx;
    int grp = c >> 6;
    float mean = g_stats[(b * 4 + grp) * 2];
    float rsig = g_stats[(b * 4 + grp) * 2 + 1];
    float gw = gn_w[c], gb = gn_b[c];
    const float* yp = g_ypre + ((b * 64 + h) * 64 + w0) * 256;
    #pragma unroll
    for (int i = 0; i < 4; i++) {
        int wl = ty + 8 * i;
        float v = yp[wl * 256 + c];
        sm[wl][tx] = fmaf((v - mean) * rsig, gw, gb);
    }
    __syncthreads();
    #pragma unroll
    for (int i = 0; i < 4; i++) {
        int cl = ty + 8 * i;
        int gi = ((b * 256 + c0 + cl) * 64 + h) * 64 + w0 + tx;
        out[gi] = x[gi] + sm[tx][cl];
    }
}

extern "C" void kernel_launch(void* const* d_in, const int* in_sizes, int n_in,
                              void* d_out, int out_size) {
    const float* x      = (const float*)d_in[0];
    const float* W_in   = (const float*)d_in[1];
    const float* W_x    = (const float*)d_in[2];
    const float* W_dt   = (const float*)d_in[3];
    const float* b_dt   = (const float*)d_in[4];
    const float* A_logs = (const float*)d_in[5];
    const float* Ds     = (const float*)d_in[6];
    const float* W_out  = (const float*)d_in[7];
    const float* gn_w   = (const float*)d_in[8];
    const float* gn_b   = (const float*)d_in[9];
    float* out = (float*)d_out;

    cudaFuncSetAttribute(k1_main, cudaFuncAttributeMaxDynamicSharedMemorySize,
                         SMEM_FLOATS * 4);
    k1_main<<<NBLK1, 256, SMEM_FLOATS * 4>>>(x, W_in, W_x, W_dt, b_dt, A_logs, Ds, W_out);
    k2_stats<<<16, 256>>>();
    k3_final<<<dim3(16, 64, 4), dim3(32, 8)>>>(x, gn_w, gn_b, out);
}

// round 13
// speedup vs baseline: 2.0082x; 1.0142x over previous
#include <cuda_runtime.h>
#include <math.h>

#define NBLK1 2048
#define LOG2E 1.44269504088896f

__device__ __align__(16) float g_ypre[4194304];   // (b,h,w,c)
__device__ float g_part[NBLK1 * 8];
__device__ float g_stats[32];

// shared-memory float offsets (float4 arrays 16B-aligned)
#define OFF_WIN   0        // [32][128]
#define OFF_WX    4096     // [64][36]  (34 used; 4cq offsets 16B-aligned)
#define OFF_WOUT  6400     // [64][32]
#define OFF_WDT   8448     // [2][64]
#define OFF_BDT2  8576     // [64]
#define OFF_DS2   8640     // [64]
#define OFF_A2    8704     // [64][17]
#define OFF_XF    9792     // [64][33]
#define OFF_XP    11904    // [64][67]
#define OFF_GZ    16192    // [64][67]
#define OFF_YS    20480    // [64][67]
#define OFF_B     24768    // [64][16]
#define OFF_C     25792    // [64][16]
#define OFF_DTSR  26816    // [64][2]
#define OFF_GACC  26944    // [8][4][2]
#define SMEM_FLOATS 27008  // 108032 B -> 2 CTAs/SM

__device__ __forceinline__ float ex2f(float x) {
    float y; asm("ex2.approx.ftz.f32 %0, %1;" : "=f"(y) : "f"(x)); return y;
}

__global__ __launch_bounds__(256, 2) void k1_main(
    const float* __restrict__ x, const float* __restrict__ W_in,
    const float* __restrict__ W_x, const float* __restrict__ W_dt,
    const float* __restrict__ b_dt, const float* __restrict__ A_logs,
    const float* __restrict__ Ds, const float* __restrict__ W_out)
{
    extern __shared__ float S[];
    const int tid = threadIdx.x;
    const int bid = blockIdx.x;

    // ---------------- load weights to smem ----------------
    for (int i = tid; i < 4096; i += 256) S[OFF_WIN + i] = W_in[i];
    for (int i = tid; i < 64 * 34; i += 256) {
        int d = i / 34, j = i - d * 34;
        S[OFF_WX + d * 36 + j] = W_x[i];
    }
    for (int i = tid; i < 2048; i += 256) {
        int d = i >> 5, g = i & 31;
        S[OFF_WOUT + d * 32 + g] = W_out[i];
    }
    if (tid < 128) S[OFF_WDT + tid] = W_dt[tid];
    if (tid < 64) {
        S[OFF_BDT2 + tid] = 2.0f * b_dt[tid];
        S[OFF_DS2 + tid]  = 2.0f * Ds[tid];
    }
    int ok = 1;
    for (int i = tid; i < 1024; i += 256) {
        int d = i >> 4, n = i & 15;
        float ae = __expf(A_logs[i]);
        if (fabsf(ae - (float)(n + 1)) > 1e-3f * (float)(n + 1)) ok = 0;
        S[OFF_A2 + d * 17 + n] = -ae * LOG2E;
    }

    // ---------------- load x tile (8 consecutive w positions) ----------------
    {
        int m0 = bid * 8;
        int b = m0 >> 12;
        int h = (m0 >> 6) & 63;
        int w0 = m0 & 63;
        const float* xb = x + b * (256 * 4096) + h * 64 + w0;
        for (int i = tid; i < 2048; i += 256) {
            int c = i >> 3, p = i & 7;
            int t = c >> 5, g = c & 31;
            S[OFF_XF + (p * 8 + t) * 33 + g] = xb[c * 4096 + p];
        }
    }
    const int fast = __syncthreads_and(ok);

    // ---------------- GEMM1: [64x32]@[32x128] -> xp(0..63), gelu(z)(64..127) --------
    {
        int rp = tid >> 3;
        int cg = tid & 7;
        float acc[2][16];
        #pragma unroll
        for (int i = 0; i < 2; i++)
            #pragma unroll
            for (int j = 0; j < 16; j++) acc[i][j] = 0.0f;
        const float4* W4 = reinterpret_cast<const float4*>(&S[OFF_WIN]);
        #pragma unroll 4
        for (int k = 0; k < 32; k++) {
            float a0 = S[OFF_XF + (2 * rp) * 33 + k];
            float a1 = S[OFF_XF + (2 * rp + 1) * 33 + k];
            #pragma unroll
            for (int q = 0; q < 4; q++) {
                float4 w = W4[k * 32 + cg * 4 + q];
                acc[0][4*q+0] = fmaf(a0, w.x, acc[0][4*q+0]);
                acc[0][4*q+1] = fmaf(a0, w.y, acc[0][4*q+1]);
                acc[0][4*q+2] = fmaf(a0, w.z, acc[0][4*q+2]);
                acc[0][4*q+3] = fmaf(a0, w.w, acc[0][4*q+3]);
                acc[1][4*q+0] = fmaf(a1, w.x, acc[1][4*q+0]);
                acc[1][4*q+1] = fmaf(a1, w.y, acc[1][4*q+1]);
                acc[1][4*q+2] = fmaf(a1, w.z, acc[1][4*q+2]);
                acc[1][4*q+3] = fmaf(a1, w.w, acc[1][4*q+3]);
            }
        }
        #pragma unroll
        for (int i = 0; i < 2; i++) {
            int row = 2 * rp + i;
            #pragma unroll
            for (int j = 0; j < 16; j++) {
                int col = cg * 16 + j;
                float v = acc[i][j];
                if (col < 64) {
                    S[OFF_XP + row * 67 + col] = v;
                } else {
                    float ge = 0.5f * v * (1.0f + erff(v * 0.70710678118f));
                    S[OFF_GZ + row * 67 + (col - 64)] = ge;
                }
            }
        }
    }
    __syncthreads();

    // ---------------- GEMM2: [64x64]@[64x34] -> dts(0,1)|B(2..17)|C(18..33) ---------
    if (tid < 128) {
        int rq = tid >> 3;
        int cq = tid & 7;
        float acc[4][4];
        #pragma unroll
        for (int i = 0; i < 4; i++)
            #pragma unroll
            for (int j = 0; j < 4; j++) acc[i][j] = 0.0f;
        #pragma unroll 4
        for (int k = 0; k < 64; k++) {
            float a0 = S[OFF_XP + (4 * rq + 0) * 67 + k];
            float a1 = S[OFF_XP + (4 * rq + 1) * 67 + k];
            float a2 = S[OFF_XP + (4 * rq + 2) * 67 + k];
            float a3 = S[OFF_XP + (4 * rq + 3) * 67 + k];
            float4 w = *reinterpret_cast<const float4*>(&S[OFF_WX + k * 36 + 4 * cq]);
            acc[0][0]=fmaf(a0,w.x,acc[0][0]); acc[0][1]=fmaf(a0,w.y,acc[0][1]); acc[0][2]=fmaf(a0,w.z,acc[0][2]); acc[0][3]=fmaf(a0,w.w,acc[0][3]);
            acc[1][0]=fmaf(a1,w.x,acc[1][0]); acc[1][1]=fmaf(a1,w.y,acc[1][1]); acc[1][2]=fmaf(a1,w.z,acc[1][2]); acc[1][3]=fmaf(a1,w.w,acc[1][3]);
            acc[2][0]=fmaf(a2,w.x,acc[2][0]); acc[2][1]=fmaf(a2,w.y,acc[2][1]); acc[2][2]=fmaf(a2,w.z,acc[2][2]); acc[2][3]=fmaf(a2,w.w,acc[2][3]);
            acc[3][0]=fmaf(a3,w.x,acc[3][0]); acc[3][1]=fmaf(a3,w.y,acc[3][1]); acc[3][2]=fmaf(a3,w.z,acc[3][2]); acc[3][3]=fmaf(a3,w.w,acc[3][3]);
        }
        #pragma unroll
        for (int i = 0; i < 4; i++) {
            int r = 4 * rq + i;
            #pragma unroll
            for (int j = 0; j < 4; j++) {
                int col = 4 * cq + j;
                float v = acc[i][j];
                if (col < 2)       S[OFF_DTSR + r * 2 + col] = v;
                else if (col < 18) S[OFF_B + r * 16 + (col - 2)] = v;
                else               S[OFF_C + r * 16 + (col - 18)] = v;
            }
        }
    } else if (tid < 192) {
        // cols 32,33 -> C[14],C[15]
        int r = tid - 128;
        float c14 = 0.0f, c15 = 0.0f;
        #pragma unroll 8
        for (int k = 0; k < 64; k++) {
            float a = S[OFF_XP + r * 67 + k];
            c14 = fmaf(a, S[OFF_WX + k * 36 + 32], c14);
            c15 = fmaf(a, S[OFF_WX + k * 36 + 33], c15);
        }
        S[OFF_C + r * 16 + 14] = c14;
        S[OFF_C + r * 16 + 15] = c15;
    }
    __syncthreads();

    // ---------------- bidirectional selective scan (4-way ILP in state loop) --------
    {
        int p  = tid >> 5;
        int d0 = tid & 31;
        float du0[8], du1[8], rr0[8], rr1[8];
        #pragma unroll
        for (int t = 0; t < 8; t++) {
            int r = p * 8 + t;
            float q0 = S[OFF_DTSR + r * 2];
            float q1 = S[OFF_DTSR + r * 2 + 1];
            float v0 = fmaf(q0, S[OFF_WDT + d0],      fmaf(q1, S[OFF_WDT + 64 + d0],      S[OFF_BDT2 + d0]));
            float v1 = fmaf(q0, S[OFF_WDT + d0 + 32], fmaf(q1, S[OFF_WDT + 96 + d0],      S[OFF_BDT2 + d0 + 32]));
            float e0 = __expf(v0), e1 = __expf(v1);
            float s0 = (v0 < -3.0f) ? e0 * (1.0f - e0 * (0.5f - 0.33333334f * e0)) : log1pf(e0);
            float s1 = (v1 < -3.0f) ? e1 * (1.0f - e1 * (0.5f - 0.33333334f * e1)) : log1pf(e1);
            du0[t] = s0 * S[OFF_XP + r * 67 + d0];
            du1[t] = s1 * S[OFF_XP + r * 67 + d0 + 32];
            // fast: decay ratio; slow: keep softplus for fallback math
            rr0[t] = fast ? ex2f(-s0 * LOG2E) : s0;
            rr1[t] = fast ? ex2f(-s1 * LOG2E) : s1;
        }
        const float* A2a = &S[OFF_A2 + d0 * 17];
        const float* A2b = &S[OFF_A2 + (d0 + 32) * 17];
        float h0[16], h1[16];
        #pragma unroll
        for (int n = 0; n < 16; n++) { h0[n] = 0.0f; h1[n] = 0.0f; }

        // forward pass
        for (int t = 0; t < 8; t++) {
            int r = p * 8 + t;
            float y0, y1;
            if (fast) {
                float w0 = rr0[t], w1 = rr1[t];
                float w0_2 = w0 * w0,   w1_2 = w1 * w1;
                float w0_4 = w0_2 * w0_2, w1_4 = w1_2 * w1_2;
                float c00 = w0, c01 = w0_2, c02 = w0_2 * w0, c03 = w0_4;
                float c10 = w1, c11 = w1_2, c12 = w1_2 * w1, c13 = w1_4;
                float dd0 = du0[t], dd1 = du1[t];
                float ya0 = 0.0f, ya1 = 0.0f, ya2 = 0.0f, ya3 = 0.0f;
                float yb0 = 0.0f, yb1 = 0.0f, yb2 = 0.0f, yb3 = 0.0f;
                const float4* Bp4 = reinterpret_cast<const float4*>(&S[OFF_B + r * 16]);
                const float4* Cp4 = reinterpret_cast<const float4*>(&S[OFF_C + r * 16]);
                #pragma unroll
                for (int jj = 0; jj < 4; jj++) {
                    float4 Bq = Bp4[jj];
                    float4 Cq = Cp4[jj];
                    int n = 4 * jj;
                    h0[n]   = fmaf(c00, h0[n],   dd0 * Bq.x);  ya0 = fmaf(h0[n],   Cq.x, ya0);
                    h0[n+1] = fmaf(c01, h0[n+1], dd0 * Bq.y);  ya1 = fmaf(h0[n+1], Cq.y, ya1);
                    h0[n+2] = fmaf(c02, h0[n+2], dd0 * Bq.z);  ya2 = fmaf(h0[n+2], Cq.z, ya2);
                    h0[n+3] = fmaf(c03, h0[n+3], dd0 * Bq.w);  ya3 = fmaf(h0[n+3], Cq.w, ya3);
                    h1[n]   = fmaf(c10, h1[n],   dd1 * Bq.x);  yb0 = fmaf(h1[n],   Cq.x, yb0);
                    h1[n+1] = fmaf(c11, h1[n+1], dd1 * Bq.y);  yb1 = fmaf(h1[n+1], Cq.y, yb1);
                    h1[n+2] = fmaf(c12, h1[n+2], dd1 * Bq.z);  yb2 = fmaf(h1[n+2], Cq.z, yb2);
                    h1[n+3] = fmaf(c13, h1[n+3], dd1 * Bq.w);  yb3 = fmaf(h1[n+3], Cq.w, yb3);
                    if (jj < 3) {
                        c00 *= w0_4; c01 *= w0_4; c02 *= w0_4; c03 *= w0_4;
                        c10 *= w1_4; c11 *= w1_4; c12 *= w1_4; c13 *= w1_4;
                    }
                }
                y0 = (ya0 + ya1) + (ya2 + ya3);
                y1 = (yb0 + yb1) + (yb2 + yb3);
            } else {
                float sp0 = rr0[t], sp1 = rr1[t];
                y0 = 0.0f; y1 = 0.0f;
                #pragma unroll
                for (int n = 0; n < 16; n++) {
                    float Bn = S[OFF_B + r * 16 + n];
                    float Cn = S[OFF_C + r * 16 + n];
                    float a0 = ex2f(sp0 * A2a[n]);
                    float a1 = ex2f(sp1 * A2b[n]);
                    h0[n] = fmaf(a0, h0[n], du0[t] * Bn);
                    h1[n] = fmaf(a1, h1[n], du1[t] * Bn);
                    y0 = fmaf(h0[n], Cn, y0);
                    y1 = fmaf(h1[n], Cn, y1);
                }
            }
            float u0 = S[OFF_XP + r * 67 + d0];
            float u1 = S[OFF_XP + r * 67 + d0 + 32];
            S[OFF_YS + r * 67 + d0]      = fmaf(u0, S[OFF_DS2 + d0], y0);
            S[OFF_YS + r * 67 + d0 + 32] = fmaf(u1, S[OFF_DS2 + d0 + 32], y1);
        }

        // backward pass + gate
        #pragma unroll
        for (int n = 0; n < 16; n++) { h0[n] = 0.0f; h1[n] = 0.0f; }
        for (int t = 7; t >= 0; t--) {
            int r = p * 8 + t;
            float y0, y1;
            if (fast) {
                float w0 = rr0[t], w1 = rr1[t];
                float w0_2 = w0 * w0,   w1_2 = w1 * w1;
                float w0_4 = w0_2 * w0_2, w1_4 = w1_2 * w1_2;
                float c00 = w0, c01 = w0_2, c02 = w0_2 * w0, c03 = w0_4;
                float c10 = w1, c11 = w1_2, c12 = w1_2 * w1, c13 = w1_4;
                float dd0 = du0[t], dd1 = du1[t];
                float ya0 = 0.0f, ya1 = 0.0f, ya2 = 0.0f, ya3 = 0.0f;
                float yb0 = 0.0f, yb1 = 0.0f, yb2 = 0.0f, yb3 = 0.0f;
                const float4* Bp4 = reinterpret_cast<const float4*>(&S[OFF_B + r * 16]);
                const float4* Cp4 = reinterpret_cast<const float4*>(&S[OFF_C + r * 16]);
                #pragma unroll
                for (int jj = 0; jj < 4; jj++) {
                    float4 Bq = Bp4[jj];
                    float4 Cq = Cp4[jj];
                    int n = 4 * jj;
                    h0[n]   = fmaf(c00, h0[n],   dd0 * Bq.x);  ya0 = fmaf(h0[n],   Cq.x, ya0);
                    h0[n+1] = fmaf(c01, h0[n+1], dd0 * Bq.y);  ya1 = fmaf(h0[n+1], Cq.y, ya1);
                    h0[n+2] = fmaf(c02, h0[n+2], dd0 * Bq.z);  ya2 = fmaf(h0[n+2], Cq.z, ya2);
                    h0[n+3] = fmaf(c03, h0[n+3], dd0 * Bq.w);  ya3 = fmaf(h0[n+3], Cq.w, ya3);
                    h1[n]   = fmaf(c10, h1[n],   dd1 * Bq.x);  yb0 = fmaf(h1[n],   Cq.x, yb0);
                    h1[n+1] = fmaf(c11, h1[n+1], dd1 * Bq.y);  yb1 = fmaf(h1[n+1], Cq.y, yb1);
                    h1[n+2] = fmaf(c12, h1[n+2], dd1 * Bq.z);  yb2 = fmaf(h1[n+2], Cq.z, yb2);
                    h1[n+3] = fmaf(c13, h1[n+3], dd1 * Bq.w);  yb3 = fmaf(h1[n+3], Cq.w, yb3);
                    if (jj < 3) {
                        c00 *= w0_4; c01 *= w0_4; c02 *= w0_4; c03 *= w0_4;
                        c10 *= w1_4; c11 *= w1_4; c12 *= w1_4; c13 *= w1_4;
                    }
                }
                y0 = (ya0 + ya1) + (ya2 + ya3);
                y1 = (yb0 + yb1) + (yb2 + yb3);
            } else {
                float sp0 = rr0[t], sp1 = rr1[t];
                y0 = 0.0f; y1 = 0.0f;
                #pragma unroll
                for (int n = 0; n < 16; n++) {
                    float Bn = S[OFF_B + r * 16 + n];
                    float Cn = S[OFF_C + r * 16 + n];
                    float a0 = ex2f(sp0 * A2a[n]);
                    float a1 = ex2f(sp1 * A2b[n]);
                    h0[n] = fmaf(a0, h0[n], du0[t] * Bn);
                    h1[n] = fmaf(a1, h1[n], du1[t] * Bn);
                    y0 = fmaf(h0[n], Cn, y0);
                    y1 = fmaf(h1[n], Cn, y1);
                }
            }
            S[OFF_YS + r * 67 + d0]      = (S[OFF_YS + r * 67 + d0]      + y0) * S[OFF_GZ + r * 67 + d0];
            S[OFF_YS + r * 67 + d0 + 32] = (S[OFF_YS + r * 67 + d0 + 32] + y1) * S[OFF_GZ + r * 67 + d0 + 32];
        }
    }
    __syncthreads();

    // ---------------- GEMM3: [64x64]@[64x32] -> y_pre + group partials ----------------
    {
        int rp = tid >> 3;
        int cq = tid & 7;
        float acc[2][4];
        #pragma unroll
        for (int i = 0; i < 2; i++)
            #pragma unroll
            for (int j = 0; j < 4; j++) acc[i][j] = 0.0f;
        const float4* W4o = reinterpret_cast<const float4*>(&S[OFF_WOUT]);
        #pragma unroll 4
        for (int k = 0; k < 64; k++) {
            float a0 = S[OFF_YS + (2 * rp) * 67 + k];
            float a1 = S[OFF_YS + (2 * rp + 1) * 67 + k];
            float4 w = W4o[k * 8 + cq];
            acc[0][0]=fmaf(a0,w.x,acc[0][0]); acc[0][1]=fmaf(a0,w.y,acc[0][1]);
            acc[0][2]=fmaf(a0,w.z,acc[0][2]); acc[0][3]=fmaf(a0,w.w,acc[0][3]);
            acc[1][0]=fmaf(a1,w.x,acc[1][0]); acc[1][1]=fmaf(a1,w.y,acc[1][1]);
            acc[1][2]=fmaf(a1,w.z,acc[1][2]); acc[1][3]=fmaf(a1,w.w,acc[1][3]);
        }
        int m0 = bid * 8;
        float s = 0.0f, ss = 0.0f;
        #pragma unroll
        for (int i = 0; i < 2; i++) {
            int row = 2 * rp + i;
            int p = row >> 3, t = row & 7;
            float4 v4 = make_float4(acc[i][0], acc[i][1], acc[i][2], acc[i][3]);
            *reinterpret_cast<float4*>(&g_ypre[(m0 + p) * 256 + t * 32 + 4 * cq]) = v4;
            s  += acc[i][0] + acc[i][1] + acc[i][2] + acc[i][3];
            ss += acc[i][0]*acc[i][0] + acc[i][1]*acc[i][1] + acc[i][2]*acc[i][2] + acc[i][3]*acc[i][3];
        }
        #pragma unroll
        for (int off = 4; off; off >>= 1) {
            s  += __shfl_down_sync(0xffffffffu, s,  off, 8);
            ss += __shfl_down_sync(0xffffffffu, ss, off, 8);
        }
        if ((tid & 7) == 0) {
            int w = tid >> 5, g = rp & 3;
            S[OFF_GACC + (w * 4 + g) * 2]     = s;
            S[OFF_GACC + (w * 4 + g) * 2 + 1] = ss;
        }
    }
    __syncthreads();
    if (tid < 8) {
        int g = tid & 3, hh = tid >> 2;
        float v = 0.0f;
        #pragma unroll
        for (int w = 0; w < 8; w++) v += S[OFF_GACC + (w * 4 + g) * 2 + hh];
        g_part[bid * 8 + g * 2 + hh] = v;
    }
}

// ---------------- kernel 2: partials -> 16 stats ----------------
__global__ void k2_stats() {
    __shared__ float ssum[256], ssq[256];
    int b = blockIdx.x >> 2, g = blockIdx.x & 3;
    int tid = threadIdx.x;
    float s = 0.0f, q = 0.0f;
    for (int j = tid; j < 512; j += 256) {
        int blk = b * 512 + j;
        s += g_part[blk * 8 + g * 2];
        q += g_part[blk * 8 + g * 2 + 1];
    }
    ssum[tid] = s; ssq[tid] = q;
    __syncthreads();
    for (int st = 128; st; st >>= 1) {
        if (tid < st) { ssum[tid] += ssum[tid + st]; ssq[tid] += ssq[tid + st]; }
        __syncthreads();
    }
    if (tid == 0) {
        float invN = 1.0f / 262144.0f;
        float mean = ssum[0] * invN;
        float var  = ssq[0] * invN - mean * mean;
        g_stats[blockIdx.x * 2]     = mean;
        g_stats[blockIdx.x * 2 + 1] = rsqrtf(var + 1e-5f);
    }
}

// ---------------- kernel 3: groupnorm affine + transpose + residual ----------------
__global__ __launch_bounds__(256) void k3_final(
    const float* __restrict__ x, const float* __restrict__ gn_w,
    const float* __restrict__ gn_b, float* __restrict__ out)
{
    __shared__ float sm[32][33];
    int tx = threadIdx.x, ty = threadIdx.y;
    int ct = blockIdx.x & 7, wt = blockIdx.x >> 3;
    int h = blockIdx.y, b = blockIdx.z;
    int c0 = ct * 32, w0 = wt * 32;
    int c = c0 + tx;
    int grp = c >> 6;
    float mean = g_stats[(b * 4 + grp) * 2];
    float rsig = g_stats[(b * 4 + grp) * 2 + 1];
    float gw = gn_w[c], gb = gn_b[c];
    const float* yp = g_ypre + ((b * 64 + h) * 64 + w0) * 256;
    #pragma unroll
    for (int i = 0; i < 4; i++) {
        int wl = ty + 8 * i;
        float v = yp[wl * 256 + c];
        sm[wl][tx] = fmaf((v - mean) * rsig, gw, gb);
    }
    __syncthreads();
    #pragma unroll
    for (int i = 0; i < 4; i++) {
        int cl = ty + 8 * i;
        int gi = ((b * 256 + c0 + cl) * 64 + h) * 64 + w0 + tx;
        out[gi] = x[gi] + sm[tx][cl];
    }
}

extern "C" void kernel_launch(void* const* d_in, const int* in_sizes, int n_in,
                              void* d_out, int out_size) {
    const float* x      = (const float*)d_in[0];
    const float* W_in   = (const float*)d_in[1];
    const float* W_x    = (const float*)d_in[2];
    const float* W_dt   = (const float*)d_in[3];
    const float* b_dt   = (const float*)d_in[4];
    const float* A_logs = (const float*)d_in[5];
    const float* Ds     = (const float*)d_in[6];
    const float* W_out  = (const float*)d_in[7];
    const float* gn_w   = (const float*)d_in[8];
    const float* gn_b   = (const float*)d_in[9];
    float* out = (float*)d_out;

    cudaFuncSetAttribute(k1_main, cudaFuncAttributeMaxDynamicSharedMemorySize,
                         SMEM_FLOATS * 4);
    k1_main<<<NBLK1, 256, SMEM_FLOATS * 4>>>(x, W_in, W_x, W_dt, b_dt, A_logs, Ds, W_out);
    k2_stats<<<16, 256>>>();
    k3_final<<<dim3(16, 64, 4), dim3(32, 8)>>>(x, gn_w, gn_b, out);
}

// round 15
// speedup vs baseline: 2.6561x; 1.3226x over previous
#include <cuda_runtime.h>
#include <math.h>

#define NBLK1 2048
#define LOG2E 1.44269504088896f

__device__ __align__(16) float g_ypre[4194304];   // (b,h,w,c)
__device__ float g_part[NBLK1 * 8];
__device__ float g_stats[32];

// shared-memory float offsets (float4 arrays 16B-aligned)
#define OFF_WIN   0        // [32][128]
#define OFF_WX    4096     // [64][36]  (34 used; 4cq offsets 16B-aligned)
#define OFF_WOUT  6400     // [64][32]
#define OFF_WDT   8448     // [2][64]
#define OFF_BDT2  8576     // [64]
#define OFF_DS2   8640     // [64]
#define OFF_A2    8704     // [64][17]
#define OFF_XF    9792     // [64][33]
#define OFF_XP    11904    // [64][67]
#define OFF_GZ    16192    // [64][67]
#define OFF_YS    20480    // [64][67]
#define OFF_B     24768    // [64][16]
#define OFF_C     25792    // [64][16]
#define OFF_DTSR  26816    // [64][2]
#define OFF_GACC  26944    // [8][4][2]
#define SMEM_FLOATS 27008  // 108032 B -> 2 CTAs/SM

__device__ __forceinline__ float ex2f(float x) {
    float y; asm("ex2.approx.ftz.f32 %0, %1;" : "=f"(y) : "f"(x)); return y;
}

__global__ __launch_bounds__(256, 2) void k1_main(
    const float* __restrict__ x, const float* __restrict__ W_in,
    const float* __restrict__ W_x, const float* __restrict__ W_dt,
    const float* __restrict__ b_dt, const float* __restrict__ A_logs,
    const float* __restrict__ Ds, const float* __restrict__ W_out)
{
    extern __shared__ float S[];
    const int tid = threadIdx.x;
    const int bid = blockIdx.x;

    // ---------------- load weights to smem ----------------
    for (int i = tid; i < 4096; i += 256) S[OFF_WIN + i] = W_in[i];
    for (int i = tid; i < 64 * 34; i += 256) {
        int d = i / 34, j = i - d * 34;
        S[OFF_WX + d * 36 + j] = W_x[i];
    }
    for (int i = tid; i < 2048; i += 256) {
        int d = i >> 5, g = i & 31;
        S[OFF_WOUT + d * 32 + g] = W_out[i];
    }
    if (tid < 128) S[OFF_WDT + tid] = W_dt[tid];
    if (tid < 64) {
        S[OFF_BDT2 + tid] = 2.0f * b_dt[tid];
        S[OFF_DS2 + tid]  = 2.0f * Ds[tid];
    }
    int ok = 1;
    for (int i = tid; i < 1024; i += 256) {
        int d = i >> 4, n = i & 15;
        float ae = __expf(A_logs[i]);
        if (fabsf(ae - (float)(n + 1)) > 1e-3f * (float)(n + 1)) ok = 0;
        S[OFF_A2 + d * 17 + n] = -ae * LOG2E;
    }

    // ---------------- load x tile (8 consecutive w positions) ----------------
    {
        int m0 = bid * 8;
        int b = m0 >> 12;
        int h = (m0 >> 6) & 63;
        int w0 = m0 & 63;
        const float* xb = x + b * (256 * 4096) + h * 64 + w0;
        for (int i = tid; i < 2048; i += 256) {
            int c = i >> 3, p = i & 7;
            int t = c >> 5, g = c & 31;
            S[OFF_XF + (p * 8 + t) * 33 + g] = xb[c * 4096 + p];
        }
    }
    const int fast = __syncthreads_and(ok);

    // ---- GEMM1: [64x32]@[32x128] -> xp | gelu(z), 4 rows x 8 cols per thread ----
    {
        const int rg  = tid >> 4;   // 0..15 -> rows 4rg..4rg+3
        const int cgp = tid & 15;   // 0..15 -> cols 8cgp..8cgp+7
        float acc[4][8];
        #pragma unroll
        for (int i = 0; i < 4; i++)
            #pragma unroll
            for (int j = 0; j < 8; j++) acc[i][j] = 0.0f;
        const float4* W4 = reinterpret_cast<const float4*>(&S[OFF_WIN]);
        #pragma unroll 4
        for (int k = 0; k < 32; k++) {
            float4 w0 = W4[k * 32 + cgp * 2];
            float4 w1 = W4[k * 32 + cgp * 2 + 1];
            #pragma unroll
            for (int i = 0; i < 4; i++) {
                float a = S[OFF_XF + (4 * rg + i) * 33 + k];
                acc[i][0] = fmaf(a, w0.x, acc[i][0]);
                acc[i][1] = fmaf(a, w0.y, acc[i][1]);
                acc[i][2] = fmaf(a, w0.z, acc[i][2]);
                acc[i][3] = fmaf(a, w0.w, acc[i][3]);
                acc[i][4] = fmaf(a, w1.x, acc[i][4]);
                acc[i][5] = fmaf(a, w1.y, acc[i][5]);
                acc[i][6] = fmaf(a, w1.z, acc[i][6]);
                acc[i][7] = fmaf(a, w1.w, acc[i][7]);
            }
        }
        if (cgp < 8) {
            #pragma unroll
            for (int i = 0; i < 4; i++) {
                int row = 4 * rg + i;
                #pragma unroll
                for (int j = 0; j < 8; j++)
                    S[OFF_XP + row * 67 + cgp * 8 + j] = acc[i][j];
            }
        } else {
            int c0 = (cgp - 8) * 8;
            #pragma unroll
            for (int i = 0; i < 4; i++) {
                int row = 4 * rg + i;
                #pragma unroll
                for (int j = 0; j < 8; j++) {
                    float v = acc[i][j];
                    S[OFF_GZ + row * 67 + c0 + j] =
                        0.5f * v * (1.0f + erff(v * 0.70710678118f));
                }
            }
        }
    }
    __syncthreads();

    // ---- GEMM2: [64x64]@[64x34], 2 rows x 4 cols on ALL 256 threads ----
    {
        const int rp = tid >> 3;   // 0..31 -> rows 2rp, 2rp+1
        const int cq = tid & 7;    // cols 4cq..4cq+3
        float acc[2][4];
        #pragma unroll
        for (int i = 0; i < 2; i++)
            #pragma unroll
            for (int j = 0; j < 4; j++) acc[i][j] = 0.0f;
        #pragma unroll 4
        for (int k = 0; k < 64; k++) {
            float a0 = S[OFF_XP + (2 * rp) * 67 + k];
            float a1 = S[OFF_XP + (2 * rp + 1) * 67 + k];
            float4 w = *reinterpret_cast<const float4*>(&S[OFF_WX + k * 36 + 4 * cq]);
            acc[0][0]=fmaf(a0,w.x,acc[0][0]); acc[0][1]=fmaf(a0,w.y,acc[0][1]);
            acc[0][2]=fmaf(a0,w.z,acc[0][2]); acc[0][3]=fmaf(a0,w.w,acc[0][3]);
            acc[1][0]=fmaf(a1,w.x,acc[1][0]); acc[1][1]=fmaf(a1,w.y,acc[1][1]);
            acc[1][2]=fmaf(a1,w.z,acc[1][2]); acc[1][3]=fmaf(a1,w.w,acc[1][3]);
        }
        #pragma unroll
        for (int i = 0; i < 2; i++) {
            int r = 2 * rp + i;
            #pragma unroll
            for (int j = 0; j < 4; j++) {
                int col = 4 * cq + j;
                float v = acc[i][j];
                if (col < 2)       S[OFF_DTSR + r * 2 + col] = v;
                else if (col < 18) S[OFF_B + r * 16 + (col - 2)] = v;
                else               S[OFF_C + r * 16 + (col - 18)] = v;
            }
        }
        // tail cols 32,33 -> C[14],C[15], on warps 6-7 (lighter main load share)
        if (tid >= 192) {
            int r = tid - 192;
            float c14 = 0.0f, c15 = 0.0f;
            #pragma unroll 8
            for (int k = 0; k < 64; k++) {
                float a = S[OFF_XP + r * 67 + k];
                c14 = fmaf(a, S[OFF_WX + k * 36 + 32], c14);
                c15 = fmaf(a, S[OFF_WX + k * 36 + 33], c15);
            }
            S[OFF_C + r * 16 + 14] = c14;
            S[OFF_C + r * 16 + 15] = c15;
        }
    }
    __syncthreads();

    // ---------------- bidirectional selective scan (4-way ILP in state loop) --------
    {
        int p  = tid >> 5;
        int d0 = tid & 31;
        float du0[8], du1[8], rr0[8], rr1[8];
        #pragma unroll
        for (int t = 0; t < 8; t++) {
            int r = p * 8 + t;
            float q0 = S[OFF_DTSR + r * 2];
            float q1 = S[OFF_DTSR + r * 2 + 1];
            float v0 = fmaf(q0, S[OFF_WDT + d0],      fmaf(q1, S[OFF_WDT + 64 + d0],      S[OFF_BDT2 + d0]));
            float v1 = fmaf(q0, S[OFF_WDT + d0 + 32], fmaf(q1, S[OFF_WDT + 96 + d0],      S[OFF_BDT2 + d0 + 32]));
            float e0 = __expf(v0), e1 = __expf(v1);
            float s0 = (v0 < -3.0f) ? e0 * (1.0f - e0 * (0.5f - 0.33333334f * e0)) : log1pf(e0);
            float s1 = (v1 < -3.0f) ? e1 * (1.0f - e1 * (0.5f - 0.33333334f * e1)) : log1pf(e1);
            du0[t] = s0 * S[OFF_XP + r * 67 + d0];
            du1[t] = s1 * S[OFF_XP + r * 67 + d0 + 32];
            rr0[t] = fast ? ex2f(-s0 * LOG2E) : s0;
            rr1[t] = fast ? ex2f(-s1 * LOG2E) : s1;
        }
        const float* A2a = &S[OFF_A2 + d0 * 17];
        const float* A2b = &S[OFF_A2 + (d0 + 32) * 17];
        float h0[16], h1[16];
        #pragma unroll
        for (int n = 0; n < 16; n++) { h0[n] = 0.0f; h1[n] = 0.0f; }

        // forward pass
        for (int t = 0; t < 8; t++) {
            int r = p * 8 + t;
            float y0, y1;
            if (fast) {
                float w0 = rr0[t], w1 = rr1[t];
                float w0_2 = w0 * w0,   w1_2 = w1 * w1;
                float w0_4 = w0_2 * w0_2, w1_4 = w1_2 * w1_2;
                float c00 = w0, c01 = w0_2, c02 = w0_2 * w0, c03 = w0_4;
                float c10 = w1, c11 = w1_2, c12 = w1_2 * w1, c13 = w1_4;
                float dd0 = du0[t], dd1 = du1[t];
                float ya0 = 0.0f, ya1 = 0.0f, ya2 = 0.0f, ya3 = 0.0f;
                float yb0 = 0.0f, yb1 = 0.0f, yb2 = 0.0f, yb3 = 0.0f;
                const float4* Bp4 = reinterpret_cast<const float4*>(&S[OFF_B + r * 16]);
                const float4* Cp4 = reinterpret_cast<const float4*>(&S[OFF_C + r * 16]);
                #pragma unroll
                for (int jj = 0; jj < 4; jj++) {
                    float4 Bq = Bp4[jj];
                    float4 Cq = Cp4[jj];
                    int n = 4 * jj;
                    h0[n]   = fmaf(c00, h0[n],   dd0 * Bq.x);  ya0 = fmaf(h0[n],   Cq.x, ya0);
                    h0[n+1] = fmaf(c01, h0[n+1], dd0 * Bq.y);  ya1 = fmaf(h0[n+1], Cq.y, ya1);
                    h0[n+2] = fmaf(c02, h0[n+2], dd0 * Bq.z);  ya2 = fmaf(h0[n+2], Cq.z, ya2);
                    h0[n+3] = fmaf(c03, h0[n+3], dd0 * Bq.w);  ya3 = fmaf(h0[n+3], Cq.w, ya3);
                    h1[n]   = fmaf(c10, h1[n],   dd1 * Bq.x);  yb0 = fmaf(h1[n],   Cq.x, yb0);
                    h1[n+1] = fmaf(c11, h1[n+1], dd1 * Bq.y);  yb1 = fmaf(h1[n+1], Cq.y, yb1);
                    h1[n+2] = fmaf(c12, h1[n+2], dd1 * Bq.z);  yb2 = fmaf(h1[n+2], Cq.z, yb2);
                    h1[n+3] = fmaf(c13, h1[n+3], dd1 * Bq.w);  yb3 = fmaf(h1[n+3], Cq.w, yb3);
                    if (jj < 3) {
                        c00 *= w0_4; c01 *= w0_4; c02 *= w0_4; c03 *= w0_4;
                        c10 *= w1_4; c11 *= w1_4; c12 *= w1_4; c13 *= w1_4;
                    }
                }
                y0 = (ya0 + ya1) + (ya2 + ya3);
                y1 = (yb0 + yb1) + (yb2 + yb3);
            } else {
                float sp0 = rr0[t], sp1 = rr1[t];
                y0 = 0.0f; y1 = 0.0f;
                #pragma unroll
                for (int n = 0; n < 16; n++) {
                    float Bn = S[OFF_B + r * 16 + n];
                    float Cn = S[OFF_C + r * 16 + n];
                    float a0 = ex2f(sp0 * A2a[n]);
                    float a1 = ex2f(sp1 * A2b[n]);
                    h0[n] = fmaf(a0, h0[n], du0[t] * Bn);
                    h1[n] = fmaf(a1, h1[n], du1[t] * Bn);
                    y0 = fmaf(h0[n], Cn, y0);
                    y1 = fmaf(h1[n], Cn, y1);
                }
            }
            float u0 = S[OFF_XP + r * 67 + d0];
            float u1 = S[OFF_XP + r * 67 + d0 + 32];
            S[OFF_YS + r * 67 + d0]      = fmaf(u0, S[OFF_DS2 + d0], y0);
            S[OFF_YS + r * 67 + d0 + 32] = fmaf(u1, S[OFF_DS2 + d0 + 32], y1);
        }

        // backward pass + gate
        #pragma unroll
        for (int n = 0; n < 16; n++) { h0[n] = 0.0f; h1[n] = 0.0f; }
        for (int t = 7; t >= 0; t--) {
            int r = p * 8 + t;
            float y0, y1;
            if (fast) {
                float w0 = rr0[t], w1 = rr1[t];
                float w0_2 = w0 * w0,   w1_2 = w1 * w1;
                float w0_4 = w0_2 * w0_2, w1_4 = w1_2 * w1_2;
                float c00 = w0, c01 = w0_2, c02 = w0_2 * w0, c03 = w0_4;
                float c10 = w1, c11 = w1_2, c12 = w1_2 * w1, c13 = w1_4;
                float dd0 = du0[t], dd1 = du1[t];
                float ya0 = 0.0f, ya1 = 0.0f, ya2 = 0.0f, ya3 = 0.0f;
                float yb0 = 0.0f, yb1 = 0.0f, yb2 = 0.0f, yb3 = 0.0f;
                const float4* Bp4 = reinterpret_cast<const float4*>(&S[OFF_B + r * 16]);
                const float4* Cp4 = reinterpret_cast<const float4*>(&S[OFF_C + r * 16]);
                #pragma unroll
                for (int jj = 0; jj < 4; jj++) {
                    float4 Bq = Bp4[jj];
                    float4 Cq = Cp4[jj];
                    int n = 4 * jj;
                    h0[n]   = fmaf(c00, h0[n],   dd0 * Bq.x);  ya0 = fmaf(h0[n],   Cq.x, ya0);
                    h0[n+1] = fmaf(c01, h0[n+1], dd0 * Bq.y);  ya1 = fmaf(h0[n+1], Cq.y, ya1);
                    h0[n+2] = fmaf(c02, h0[n+2], dd0 * Bq.z);  ya2 = fmaf(h0[n+2], Cq.z, ya2);
                    h0[n+3] = fmaf(c03, h0[n+3], dd0 * Bq.w);  ya3 = fmaf(h0[n+3], Cq.w, ya3);
                    h1[n]   = fmaf(c10, h1[n],   dd1 * Bq.x);  yb0 = fmaf(h1[n],   Cq.x, yb0);
                    h1[n+1] = fmaf(c11, h1[n+1], dd1 * Bq.y);  yb1 = fmaf(h1[n+1], Cq.y, yb1);
                    h1[n+2] = fmaf(c12, h1[n+2], dd1 * Bq.z);  yb2 = fmaf(h1[n+2], Cq.z, yb2);
                    h1[n+3] = fmaf(c13, h1[n+3], dd1 * Bq.w);  yb3 = fmaf(h1[n+3], Cq.w, yb3);
                    if (jj < 3) {
                        c00 *= w0_4; c01 *= w0_4; c02 *= w0_4; c03 *= w0_4;
                        c10 *= w1_4; c11 *= w1_4; c12 *= w1_4; c13 *= w1_4;
                    }
                }
                y0 = (ya0 + ya1) + (ya2 + ya3);
                y1 = (yb0 + yb1) + (yb2 + yb3);
            } else {
                float sp0 = rr0[t], sp1 = rr1[t];
                y0 = 0.0f; y1 = 0.0f;
                #pragma unroll
                for (int n = 0; n < 16; n++) {
                    float Bn = S[OFF_B + r * 16 + n];
                    float Cn = S[OFF_C + r * 16 + n];
                    float a0 = ex2f(sp0 * A2a[n]);
                    float a1 = ex2f(sp1 * A2b[n]);
                    h0[n] = fmaf(a0, h0[n], du0[t] * Bn);
                    h1[n] = fmaf(a1, h1[n], du1[t] * Bn);
                    y0 = fmaf(h0[n], Cn, y0);
                    y1 = fmaf(h1[n], Cn, y1);
                }
            }
            S[OFF_YS + r * 67 + d0]      = (S[OFF_YS + r * 67 + d0]      + y0) * S[OFF_GZ + r * 67 + d0];
            S[OFF_YS + r * 67 + d0 + 32] = (S[OFF_YS + r * 67 + d0 + 32] + y1) * S[OFF_GZ + r * 67 + d0 + 32];
        }
    }
    __syncthreads();

    // ---------------- GEMM3: [64x64]@[64x32] -> y_pre + group partials ----------------
    {
        int rp = tid >> 3;
        int cq = tid & 7;
        float acc[2][4];
        #pragma unroll
        for (int i = 0; i < 2; i++)
            #pragma unroll
            for (int j = 0; j < 4; j++) acc[i][j] = 0.0f;
        const float4* W4o = reinterpret_cast<const float4*>(&S[OFF_WOUT]);
        #pragma unroll 4
        for (int k = 0; k < 64; k++) {
            float a0 = S[OFF_YS + (2 * rp) * 67 + k];
            float a1 = S[OFF_YS + (2 * rp + 1) * 67 + k];
            float4 w = W4o[k * 8 + cq];
            acc[0][0]=fmaf(a0,w.x,acc[0][0]); acc[0][1]=fmaf(a0,w.y,acc[0][1]);
            acc[0][2]=fmaf(a0,w.z,acc[0][2]); acc[0][3]=fmaf(a0,w.w,acc[0][3]);
            acc[1][0]=fmaf(a1,w.x,acc[1][0]); acc[1][1]=fmaf(a1,w.y,acc[1][1]);
            acc[1][2]=fmaf(a1,w.z,acc[1][2]); acc[1][3]=fmaf(a1,w.w,acc[1][3]);
        }
        int m0 = bid * 8;
        float s = 0.0f, ss = 0.0f;
        #pragma unroll
        for (int i = 0; i < 2; i++) {
            int row = 2 * rp + i;
            int p = row >> 3, t = row & 7;
            float4 v4 = make_float4(acc[i][0], acc[i][1], acc[i][2], acc[i][3]);
            *reinterpret_cast<float4*>(&g_ypre[(m0 + p) * 256 + t * 32 + 4 * cq]) = v4;
            s  += acc[i][0] + acc[i][1] + acc[i][2] + acc[i][3];
            ss += acc[i][0]*acc[i][0] + acc[i][1]*acc[i][1] + acc[i][2]*acc[i][2] + acc[i][3]*acc[i][3];
        }
        #pragma unroll
        for (int off = 4; off; off >>= 1) {
            s  += __shfl_down_sync(0xffffffffu, s,  off, 8);
            ss += __shfl_down_sync(0xffffffffu, ss, off, 8);
        }
        if ((tid & 7) == 0) {
            int w = tid >> 5, g = rp & 3;
            S[OFF_GACC + (w * 4 + g) * 2]     = s;
            S[OFF_GACC + (w * 4 + g) * 2 + 1] = ss;
        }
    }
    __syncthreads();
    if (tid < 8) {
        int g = tid & 3, hh = tid >> 2;
        float v = 0.0f;
        #pragma unroll
        for (int w = 0; w < 8; w++) v += S[OFF_GACC + (w * 4 + g) * 2 + hh];
        g_part[bid * 8 + g * 2 + hh] = v;
    }
}

// ---------------- kernel 2: partials -> 16 stats ----------------
__global__ void k2_stats() {
    __shared__ float ssum[256], ssq[256];
    int b = blockIdx.x >> 2, g = blockIdx.x & 3;
    int tid = threadIdx.x;
    float s = 0.0f, q = 0.0f;
    for (int j = tid; j < 512; j += 256) {
        int blk = b * 512 + j;
        s += g_part[blk * 8 + g * 2];
        q += g_part[blk * 8 + g * 2 + 1];
    }
    ssum[tid] = s; ssq[tid] = q;
    __syncthreads();
    for (int st = 128; st; st >>= 1) {
        if (tid < st) { ssum[tid] += ssum[tid + st]; ssq[tid] += ssq[tid + st]; }
        __syncthreads();
    }
    if (tid == 0) {
        float invN = 1.0f / 262144.0f;
        float mean = ssum[0] * invN;
        float var  = ssq[0] * invN - mean * mean;
        g_stats[blockIdx.x * 2]     = mean;
        g_stats[blockIdx.x * 2 + 1] = rsqrtf(var + 1e-5f);
    }
}

// ---------------- kernel 3: groupnorm affine + transpose + residual ----------------
__global__ __launch_bounds__(256) void k3_final(
    const float* __restrict__ x, const float* __restrict__ gn_w,
    const float* __restrict__ gn_b, float* __restrict__ out)
{
    __shared__ float sm[32][33];
    int tx = threadIdx.x, ty = threadIdx.y;
    int ct = blockIdx.x & 7, wt = blockIdx.x >> 3;
    int h = blockIdx.y, b = blockIdx.z;
    int c0 = ct * 32, w0 = wt * 32;
    int c = c0 + tx;
    int grp = c >> 6;
    float mean = g_stats[(b * 4 + grp) * 2];
    float rsig = g_stats[(b * 4 + grp) * 2 + 1];
    float gw = gn_w[c], gb = gn_b[c];
    const float* yp = g_ypre + ((b * 64 + h) * 64 + w0) * 256;
    #pragma unroll
    for (int i = 0; i < 4; i++) {
        int wl = ty + 8 * i;
        float v = yp[wl * 256 + c];
        sm[wl][tx] = fmaf((v - mean) * rsig, gw, gb);
    }
    __syncthreads();
    #pragma unroll
    for (int i = 0; i < 4; i++) {
        int cl = ty + 8 * i;
        int gi = ((b * 256 + c0 + cl) * 64 + h) * 64 + w0 + tx;
        out[gi] = x[gi] + sm[tx][cl];
    }
}

extern "C" void kernel_launch(void* const* d_in, const int* in_sizes, int n_in,
                              void* d_out, int out_size) {
    const float* x      = (const float*)d_in[0];
    const float* W_in   = (const float*)d_in[1];
    const float* W_x    = (const float*)d_in[2];
    const float* W_dt   = (const float*)d_in[3];
    const float* b_dt   = (const float*)d_in[4];
    const float* A_logs = (const float*)d_in[5];
    const float* Ds     = (const float*)d_in[6];
    const float* W_out  = (const float*)d_in[7];
    const float* gn_w   = (const float*)d_in[8];
    const float* gn_b   = (const float*)d_in[9];
    float* out = (float*)d_out;

    cudaFuncSetAttribute(k1_main, cudaFuncAttributeMaxDynamicSharedMemorySize,
                         SMEM_FLOATS * 4);
    k1_main<<<NBLK1, 256, SMEM_FLOATS * 4>>>(x, W_in, W_x, W_dt, b_dt, A_logs, Ds, W_out);
    k2_stats<<<16, 256>>>();
    k3_final<<<dim3(16, 64, 4), dim3(32, 8)>>>(x, gn_w, gn_b, out);
}

// round 16
// speedup vs baseline: 2.7036x; 1.0179x over previous
#include <cuda_runtime.h>
#include <math.h>

#define NBLK1 2048
#define LOG2E 1.44269504088896f
typedef unsigned long long ULL;

__device__ __align__(16) float g_ypre[4194304];   // (b,h,w,c)
__device__ float g_part[NBLK1 * 8];
__device__ float g_stats[32];

// shared-memory float offsets (packed accesses 8B/16B aligned)
#define OFF_WIN   0        // [32][128]
#define OFF_WX    4096     // [64][36]  (34 used)
#define OFF_WOUT  6400     // [64][32]
#define OFF_WDT   8448     // [2][64]
#define OFF_BDT2  8576     // [64]
#define OFF_DS2   8640     // [64]
#define OFF_A2    8704     // [64][17]
#define OFF_XF    9792     // [64][33]
#define OFF_XP    11904    // [64][68]
#define OFF_GZ    16256    // [64][68]
#define OFF_YS    20608    // [64][68]
#define OFF_B     24960    // [64][16]
#define OFF_C     25984    // [64][16]
#define OFF_DTSR  27008    // [64][2]
#define OFF_GACC  27136    // [8][4][2]
#define SMEM_FLOATS 27200  // 108800 B -> 2 CTAs/SM

__device__ __forceinline__ float ex2f(float x) {
    float y; asm("ex2.approx.ftz.f32 %0, %1;" : "=f"(y) : "f"(x)); return y;
}
__device__ __forceinline__ ULL pack2(float lo, float hi) {
    ULL d; asm("mov.b64 %0, {%1, %2};" : "=l"(d) : "f"(lo), "f"(hi)); return d;
}
__device__ __forceinline__ ULL dup2(float v) { return pack2(v, v); }
__device__ __forceinline__ void unpack2(ULL v, float& lo, float& hi) {
    asm("mov.b64 {%0, %1}, %2;" : "=f"(lo), "=f"(hi) : "l"(v));
}
__device__ __forceinline__ ULL f2fma(ULL a, ULL b, ULL c) {
    ULL d; asm("fma.rn.f32x2 %0, %1, %2, %3;" : "=l"(d) : "l"(a), "l"(b), "l"(c)); return d;
}

__global__ __launch_bounds__(256, 2) void k1_main(
    const float* __restrict__ x, const float* __restrict__ W_in,
    const float* __restrict__ W_x, const float* __restrict__ W_dt,
    const float* __restrict__ b_dt, const float* __restrict__ A_logs,
    const float* __restrict__ Ds, const float* __restrict__ W_out)
{
    extern __shared__ float S[];
    const int tid = threadIdx.x;
    const int bid = blockIdx.x;

    // ---------------- load weights to smem ----------------
    for (int i = tid; i < 4096; i += 256) S[OFF_WIN + i] = W_in[i];
    for (int i = tid; i < 64 * 34; i += 256) {
        int d = i / 34, j = i - d * 34;
        S[OFF_WX + d * 36 + j] = W_x[i];
    }
    for (int i = tid; i < 2048; i += 256) S[OFF_WOUT + i] = W_out[i];
    if (tid < 128) S[OFF_WDT + tid] = W_dt[tid];
    if (tid < 64) {
        S[OFF_BDT2 + tid] = 2.0f * b_dt[tid];
        S[OFF_DS2 + tid]  = 2.0f * Ds[tid];
    }
    int ok = 1;
    for (int i = tid; i < 1024; i += 256) {
        int d = i >> 4, n = i & 15;
        float ae = __expf(A_logs[i]);
        if (fabsf(ae - (float)(n + 1)) > 1e-3f * (float)(n + 1)) ok = 0;
        S[OFF_A2 + d * 17 + n] = -ae * LOG2E;
    }

    // ---------------- load x tile (8 consecutive w positions) ----------------
    {
        int m0 = bid * 8;
        int b = m0 >> 12;
        int h = (m0 >> 6) & 63;
        int w0 = m0 & 63;
        const float* xb = x + b * (256 * 4096) + h * 64 + w0;
        for (int i = tid; i < 2048; i += 256) {
            int c = i >> 3, p = i & 7;
            int t = c >> 5, g = c & 31;
            S[OFF_XF + (p * 8 + t) * 33 + g] = xb[c * 4096 + p];
        }
    }
    const int fast = __syncthreads_and(ok);

    // ---- GEMM1 (packed f32x2): [64x32]@[32x128], 4 rows x 8 cols per thread ----
    {
        const int rg  = tid >> 4;   // rows 4rg..4rg+3
        const int cgp = tid & 15;   // cols 8cgp..8cgp+7
        ULL acc[4][4];
        #pragma unroll
        for (int i = 0; i < 4; i++)
            #pragma unroll
            for (int j = 0; j < 4; j++) acc[i][j] = 0ULL;
        #pragma unroll 4
        for (int k = 0; k < 32; k++) {
            const ulonglong2* wp = reinterpret_cast<const ulonglong2*>(&S[OFF_WIN + k * 128 + cgp * 8]);
            ulonglong2 wA = wp[0], wB = wp[1];
            #pragma unroll
            for (int i = 0; i < 4; i++) {
                ULL ap = dup2(S[OFF_XF + (4 * rg + i) * 33 + k]);
                acc[i][0] = f2fma(ap, wA.x, acc[i][0]);
                acc[i][1] = f2fma(ap, wA.y, acc[i][1]);
                acc[i][2] = f2fma(ap, wB.x, acc[i][2]);
                acc[i][3] = f2fma(ap, wB.y, acc[i][3]);
            }
        }
        if (cgp < 8) {
            #pragma unroll
            for (int i = 0; i < 4; i++) {
                ULL* X = reinterpret_cast<ULL*>(&S[OFF_XP + (4 * rg + i) * 68 + cgp * 8]);
                X[0] = acc[i][0]; X[1] = acc[i][1]; X[2] = acc[i][2]; X[3] = acc[i][3];
            }
        } else {
            int c0 = (cgp - 8) * 8;
            #pragma unroll
            for (int i = 0; i < 4; i++) {
                int row = 4 * rg + i;
                #pragma unroll
                for (int j = 0; j < 4; j++) {
                    float lo, hi;
                    unpack2(acc[i][j], lo, hi);
                    S[OFF_GZ + row * 68 + c0 + 2 * j]     = 0.5f * lo * (1.0f + erff(lo * 0.70710678118f));
                    S[OFF_GZ + row * 68 + c0 + 2 * j + 1] = 0.5f * hi * (1.0f + erff(hi * 0.70710678118f));
                }
            }
        }
    }
    __syncthreads();

    // ---- GEMM2 (packed): [64x64]@[64x34], 2 rows x 4 cols on ALL 256 threads ----
    {
        const int rp = tid >> 3;   // rows 2rp, 2rp+1
        const int cq = tid & 7;    // cols 4cq..4cq+3
        ULL acc0[2], acc1[2];
        acc0[0] = acc0[1] = acc1[0] = acc1[1] = 0ULL;
        #pragma unroll 4
        for (int k = 0; k < 64; k++) {
            ulonglong2 w = *reinterpret_cast<const ulonglong2*>(&S[OFF_WX + k * 36 + 4 * cq]);
            ULL a0 = dup2(S[OFF_XP + (2 * rp) * 68 + k]);
            ULL a1 = dup2(S[OFF_XP + (2 * rp + 1) * 68 + k]);
            acc0[0] = f2fma(a0, w.x, acc0[0]);
            acc0[1] = f2fma(a0, w.y, acc0[1]);
            acc1[0] = f2fma(a1, w.x, acc1[0]);
            acc1[1] = f2fma(a1, w.y, acc1[1]);
        }
        #pragma unroll
        for (int i = 0; i < 2; i++) {
            int r = 2 * rp + i;
            ULL v0 = i ? acc1[0] : acc0[0];
            ULL v1 = i ? acc1[1] : acc0[1];
            #pragma unroll
            for (int pp = 0; pp < 2; pp++) {
                int c0 = 4 * cq + 2 * pp;
                ULL v = pp ? v1 : v0;
                if (c0 == 0)
                    *reinterpret_cast<ULL*>(&S[OFF_DTSR + r * 2]) = v;
                else if (c0 < 18)
                    *reinterpret_cast<ULL*>(&S[OFF_B + r * 16 + (c0 - 2)]) = v;
                else
                    *reinterpret_cast<ULL*>(&S[OFF_C + r * 16 + (c0 - 18)]) = v;
            }
        }
        // tail cols 32,33 -> C[14],C[15] on warps 6-7
        if (tid >= 192) {
            int r = tid - 192;
            ULL acc = 0ULL;
            #pragma unroll 8
            for (int k = 0; k < 64; k++) {
                ULL w = *reinterpret_cast<const ULL*>(&S[OFF_WX + k * 36 + 32]);
                acc = f2fma(dup2(S[OFF_XP + r * 68 + k]), w, acc);
            }
            *reinterpret_cast<ULL*>(&S[OFF_C + r * 16 + 14]) = acc;
        }
    }
    __syncthreads();

    // ---------------- bidirectional selective scan (scalar, 4-way ILP) --------
    {
        int p  = tid >> 5;
        int d0 = tid & 31;
        float du0[8], du1[8], rr0[8], rr1[8];
        #pragma unroll
        for (int t = 0; t < 8; t++) {
            int r = p * 8 + t;
            float q0 = S[OFF_DTSR + r * 2];
            float q1 = S[OFF_DTSR + r * 2 + 1];
            float v0 = fmaf(q0, S[OFF_WDT + d0],      fmaf(q1, S[OFF_WDT + 64 + d0],      S[OFF_BDT2 + d0]));
            float v1 = fmaf(q0, S[OFF_WDT + d0 + 32], fmaf(q1, S[OFF_WDT + 96 + d0],      S[OFF_BDT2 + d0 + 32]));
            float e0 = __expf(v0), e1 = __expf(v1);
            float s0 = (v0 < -3.0f) ? e0 * (1.0f - e0 * (0.5f - 0.33333334f * e0)) : log1pf(e0);
            float s1 = (v1 < -3.0f) ? e1 * (1.0f - e1 * (0.5f - 0.33333334f * e1)) : log1pf(e1);
            du0[t] = s0 * S[OFF_XP + r * 68 + d0];
            du1[t] = s1 * S[OFF_XP + r * 68 + d0 + 32];
            rr0[t] = fast ? ex2f(-s0 * LOG2E) : s0;
            rr1[t] = fast ? ex2f(-s1 * LOG2E) : s1;
        }
        const float* A2a = &S[OFF_A2 + d0 * 17];
        const float* A2b = &S[OFF_A2 + (d0 + 32) * 17];
        float h0[16], h1[16];
        #pragma unroll
        for (int n = 0; n < 16; n++) { h0[n] = 0.0f; h1[n] = 0.0f; }

        // forward pass
        for (int t = 0; t < 8; t++) {
            int r = p * 8 + t;
            float y0, y1;
            if (fast) {
                float w0 = rr0[t], w1 = rr1[t];
                float w0_2 = w0 * w0,   w1_2 = w1 * w1;
                float w0_4 = w0_2 * w0_2, w1_4 = w1_2 * w1_2;
                float c00 = w0, c01 = w0_2, c02 = w0_2 * w0, c03 = w0_4;
                float c10 = w1, c11 = w1_2, c12 = w1_2 * w1, c13 = w1_4;
                float dd0 = du0[t], dd1 = du1[t];
                float ya0 = 0.0f, ya1 = 0.0f, ya2 = 0.0f, ya3 = 0.0f;
                float yb0 = 0.0f, yb1 = 0.0f, yb2 = 0.0f, yb3 = 0.0f;
                const float4* Bp4 = reinterpret_cast<const float4*>(&S[OFF_B + r * 16]);
                const float4* Cp4 = reinterpret_cast<const float4*>(&S[OFF_C + r * 16]);
                #pragma unroll
                for (int jj = 0; jj < 4; jj++) {
                    float4 Bq = Bp4[jj];
                    float4 Cq = Cp4[jj];
                    int n = 4 * jj;
                    h0[n]   = fmaf(c00, h0[n],   dd0 * Bq.x);  ya0 = fmaf(h0[n],   Cq.x, ya0);
                    h0[n+1] = fmaf(c01, h0[n+1], dd0 * Bq.y);  ya1 = fmaf(h0[n+1], Cq.y, ya1);
                    h0[n+2] = fmaf(c02, h0[n+2], dd0 * Bq.z);  ya2 = fmaf(h0[n+2], Cq.z, ya2);
                    h0[n+3] = fmaf(c03, h0[n+3], dd0 * Bq.w);  ya3 = fmaf(h0[n+3], Cq.w, ya3);
                    h1[n]   = fmaf(c10, h1[n],   dd1 * Bq.x);  yb0 = fmaf(h1[n],   Cq.x, yb0);
                    h1[n+1] = fmaf(c11, h1[n+1], dd1 * Bq.y);  yb1 = fmaf(h1[n+1], Cq.y, yb1);
                    h1[n+2] = fmaf(c12, h1[n+2], dd1 * Bq.z);  yb2 = fmaf(h1[n+2], Cq.z, yb2);
                    h1[n+3] = fmaf(c13, h1[n+3], dd1 * Bq.w);  yb3 = fmaf(h1[n+3], Cq.w, yb3);
                    if (jj < 3) {
                        c00 *= w0_4; c01 *= w0_4; c02 *= w0_4; c03 *= w0_4;
                        c10 *= w1_4; c11 *= w1_4; c12 *= w1_4; c13 *= w1_4;
                    }
                }
                y0 = (ya0 + ya1) + (ya2 + ya3);
                y1 = (yb0 + yb1) + (yb2 + yb3);
            } else {
                float sp0 = rr0[t], sp1 = rr1[t];
                y0 = 0.0f; y1 = 0.0f;
                #pragma unroll
                for (int n = 0; n < 16; n++) {
                    float Bn = S[OFF_B + r * 16 + n];
                    float Cn = S[OFF_C + r * 16 + n];
                    float a0 = ex2f(sp0 * A2a[n]);
                    float a1 = ex2f(sp1 * A2b[n]);
                    h0[n] = fmaf(a0, h0[n], du0[t] * Bn);
                    h1[n] = fmaf(a1, h1[n], du1[t] * Bn);
                    y0 = fmaf(h0[n], Cn, y0);
                    y1 = fmaf(h1[n], Cn, y1);
                }
            }
            float u0 = S[OFF_XP + r * 68 + d0];
            float u1 = S[OFF_XP + r * 68 + d0 + 32];
            S[OFF_YS + r * 68 + d0]      = fmaf(u0, S[OFF_DS2 + d0], y0);
            S[OFF_YS + r * 68 + d0 + 32] = fmaf(u1, S[OFF_DS2 + d0 + 32], y1);
        }

        // backward pass + gate
        #pragma unroll
        for (int n = 0; n < 16; n++) { h0[n] = 0.0f; h1[n] = 0.0f; }
        for (int t = 7; t >= 0; t--) {
            int r = p * 8 + t;
            float y0, y1;
            if (fast) {
                float w0 = rr0[t], w1 = rr1[t];
                float w0_2 = w0 * w0,   w1_2 = w1 * w1;
                float w0_4 = w0_2 * w0_2, w1_4 = w1_2 * w1_2;
                float c00 = w0, c01 = w0_2, c02 = w0_2 * w0, c03 = w0_4;
                float c10 = w1, c11 = w1_2, c12 = w1_2 * w1, c13 = w1_4;
                float dd0 = du0[t], dd1 = du1[t];
                float ya0 = 0.0f, ya1 = 0.0f, ya2 = 0.0f, ya3 = 0.0f;
                float yb0 = 0.0f, yb1 = 0.0f, yb2 = 0.0f, yb3 = 0.0f;
                const float4* Bp4 = reinterpret_cast<const float4*>(&S[OFF_B + r * 16]);
                const float4* Cp4 = reinterpret_cast<const float4*>(&S[OFF_C + r * 16]);
                #pragma unroll
                for (int jj = 0; jj < 4; jj++) {
                    float4 Bq = Bp4[jj];
                    float4 Cq = Cp4[jj];
                    int n = 4 * jj;
                    h0[n]   = fmaf(c00, h0[n],   dd0 * Bq.x);  ya0 = fmaf(h0[n],   Cq.x, ya0);
                    h0[n+1] = fmaf(c01, h0[n+1], dd0 * Bq.y);  ya1 = fmaf(h0[n+1], Cq.y, ya1);
                    h0[n+2] = fmaf(c02, h0[n+2], dd0 * Bq.z);  ya2 = fmaf(h0[n+2], Cq.z, ya2);
                    h0[n+3] = fmaf(c03, h0[n+3], dd0 * Bq.w);  ya3 = fmaf(h0[n+3], Cq.w, ya3);
                    h1[n]   = fmaf(c10, h1[n],   dd1 * Bq.x);  yb0 = fmaf(h1[n],   Cq.x, yb0);
                    h1[n+1] = fmaf(c11, h1[n+1], dd1 * Bq.y);  yb1 = fmaf(h1[n+1], Cq.y, yb1);
                    h1[n+2] = fmaf(c12, h1[n+2], dd1 * Bq.z);  yb2 = fmaf(h1[n+2], Cq.z, yb2);
                    h1[n+3] = fmaf(c13, h1[n+3], dd1 * Bq.w);  yb3 = fmaf(h1[n+3], Cq.w, yb3);
                    if (jj < 3) {
                        c00 *= w0_4; c01 *= w0_4; c02 *= w0_4; c03 *= w0_4;
                        c10 *= w1_4; c11 *= w1_4; c12 *= w1_4; c13 *= w1_4;
                    }
                }
                y0 = (ya0 + ya1) + (ya2 + ya3);
                y1 = (yb0 + yb1) + (yb2 + yb3);
            } else {
                float sp0 = rr0[t], sp1 = rr1[t];
                y0 = 0.0f; y1 = 0.0f;
                #pragma unroll
                for (int n = 0; n < 16; n++) {
                    float Bn = S[OFF_B + r * 16 + n];
                    float Cn = S[OFF_C + r * 16 + n];
                    float a0 = ex2f(sp0 * A2a[n]);
                    float a1 = ex2f(sp1 * A2b[n]);
                    h0[n] = fmaf(a0, h0[n], du0[t] * Bn);
                    h1[n] = fmaf(a1, h1[n], du1[t] * Bn);
                    y0 = fmaf(h0[n], Cn, y0);
                    y1 = fmaf(h1[n], Cn, y1);
                }
            }
            S[OFF_YS + r * 68 + d0]      = (S[OFF_YS + r * 68 + d0]      + y0) * S[OFF_GZ + r * 68 + d0];
            S[OFF_YS + r * 68 + d0 + 32] = (S[OFF_YS + r * 68 + d0 + 32] + y1) * S[OFF_GZ + r * 68 + d0 + 32];
        }
    }
    __syncthreads();

    // ---- GEMM3 (packed): [64x64]@[64x32] -> y_pre + group partials ----
    {
        int rp = tid >> 3;
        int cq = tid & 7;
        ULL acc0[2], acc1[2];
        acc0[0] = acc0[1] = acc1[0] = acc1[1] = 0ULL;
        #pragma unroll 4
        for (int k = 0; k < 64; k++) {
            ulonglong2 w = *reinterpret_cast<const ulonglong2*>(&S[OFF_WOUT + k * 32 + 4 * cq]);
            ULL a0 = dup2(S[OFF_YS + (2 * rp) * 68 + k]);
            ULL a1 = dup2(S[OFF_YS + (2 * rp + 1) * 68 + k]);
            acc0[0] = f2fma(a0, w.x, acc0[0]);
            acc0[1] = f2fma(a0, w.y, acc0[1]);
            acc1[0] = f2fma(a1, w.x, acc1[0]);
            acc1[1] = f2fma(a1, w.y, acc1[1]);
        }
        int m0 = bid * 8;
        float s = 0.0f, ss = 0.0f;
        #pragma unroll
        for (int i = 0; i < 2; i++) {
            int row = 2 * rp + i;
            int p = row >> 3, t = row & 7;
            ULL v0 = i ? acc1[0] : acc0[0];
            ULL v1 = i ? acc1[1] : acc0[1];
            ULL* dst = reinterpret_cast<ULL*>(&g_ypre[(m0 + p) * 256 + t * 32 + 4 * cq]);
            dst[0] = v0; dst[1] = v1;
            float a, b, c, d;
            unpack2(v0, a, b); unpack2(v1, c, d);
            s  += (a + b) + (c + d);
            ss += (a * a + b * b) + (c * c + d * d);
        }
        #pragma unroll
        for (int off = 4; off; off >>= 1) {
            s  += __shfl_down_sync(0xffffffffu, s,  off, 8);
            ss += __shfl_down_sync(0xffffffffu, ss, off, 8);
        }
        if ((tid & 7) == 0) {
            int w = tid >> 5, g = rp & 3;
            S[OFF_GACC + (w * 4 + g) * 2]     = s;
            S[OFF_GACC + (w * 4 + g) * 2 + 1] = ss;
        }
    }
    __syncthreads();
    if (tid < 8) {
        int g = tid & 3, hh = tid >> 2;
        float v = 0.0f;
        #pragma unroll
        for (int w = 0; w < 8; w++) v += S[OFF_GACC + (w * 4 + g) * 2 + hh];
        g_part[bid * 8 + g * 2 + hh] = v;
    }
}

// ---------------- kernel 2: partials -> 16 stats ----------------
__global__ void k2_stats() {
    __shared__ float ssum[256], ssq[256];
    int b = blockIdx.x >> 2, g = blockIdx.x & 3;
    int tid = threadIdx.x;
    float s = 0.0f, q = 0.0f;
    for (int j = tid; j < 512; j += 256) {
        int blk = b * 512 + j;
        s += g_part[blk * 8 + g * 2];
        q += g_part[blk * 8 + g * 2 + 1];
    }
    ssum[tid] = s; ssq[tid] = q;
    __syncthreads();
    for (int st = 128; st; st >>= 1) {
        if (tid < st) { ssum[tid] += ssum[tid + st]; ssq[tid] += ssq[tid + st]; }
        __syncthreads();
    }
    if (tid == 0) {
        float invN = 1.0f / 262144.0f;
        float mean = ssum[0] * invN;
        float var  = ssq[0] * invN - mean * mean;
        g_stats[blockIdx.x * 2]     = mean;
        g_stats[blockIdx.x * 2 + 1] = rsqrtf(var + 1e-5f);
    }
}

// ---------------- kernel 3: groupnorm affine + transpose + residual ----------------
__global__ __launch_bounds__(256) void k3_final(
    const float* __restrict__ x, const float* __restrict__ gn_w,
    const float* __restrict__ gn_b, float* __restrict__ out)
{
    __shared__ float sm[32][33];
    int tx = threadIdx.x, ty = threadIdx.y;
    int ct = blockIdx.x & 7, wt = blockIdx.x >> 3;
    int h = blockIdx.y, b = blockIdx.z;
    int c0 = ct * 32, w0 = wt * 32;
    int c = c0 + tx;
    int grp = c >> 6;
    float mean = g_stats[(b * 4 + grp) * 2];
    float rsig = g_stats[(b * 4 + grp) * 2 + 1];
    float gw = gn_w[c], gb = gn_b[c];
    const float* yp = g_ypre + ((b * 64 + h) * 64 + w0) * 256;
    #pragma unroll
    for (int i = 0; i < 4; i++) {
        int wl = ty + 8 * i;
        float v = yp[wl * 256 + c];
        sm[wl][tx] = fmaf((v - mean) * rsig, gw, gb);
    }
    __syncthreads();
    #pragma unroll
    for (int i = 0; i < 4; i++) {
        int cl = ty + 8 * i;
        int gi = ((b * 256 + c0 + cl) * 64 + h) * 64 + w0 + tx;
        out[gi] = x[gi] + sm[tx][cl];
    }
}

extern "C" void kernel_launch(void* const* d_in, const int* in_sizes, int n_in,
                              void* d_out, int out_size) {
    const float* x      = (const float*)d_in[0];
    const float* W_in   = (const float*)d_in[1];
    const float* W_x    = (const float*)d_in[2];
    const float* W_dt   = (const float*)d_in[3];
    const float* b_dt   = (const float*)d_in[4];
    const float* A_logs = (const float*)d_in[5];
    const float* Ds     = (const float*)d_in[6];
    const float* W_out  = (const float*)d_in[7];
    const float* gn_w   = (const float*)d_in[8];
    const float* gn_b   = (const float*)d_in[9];
    float* out = (float*)d_out;

    cudaFuncSetAttribute(k1_main, cudaFuncAttributeMaxDynamicSharedMemorySize,
                         SMEM_FLOATS * 4);
    k1_main<<<NBLK1, 256, SMEM_FLOATS * 4>>>(x, W_in, W_x, W_dt, b_dt, A_logs, Ds, W_out);
    k2_stats<<<16, 256>>>();
    k3_final<<<dim3(16, 64, 4), dim3(32, 8)>>>(x, gn_w, gn_b, out);
}

// round 17
// speedup vs baseline: 2.9331x; 1.0849x over previous
#include <cuda_runtime.h>
#include <math.h>

#define NBLK1 2048
#define LOG2E 1.44269504088896f
typedef unsigned long long ULL;

__device__ __align__(16) float g_ypre[4194304];   // (b,h,w,c)
__device__ float g_part[NBLK1 * 8];
__device__ float g_stats[32];

// shared-memory float offsets (packed accesses 8B/16B aligned)
#define OFF_WIN   0        // [32][128]
#define OFF_WX    4096     // [64][36]  (34 used)
#define OFF_WOUT  6400     // [64][32]
#define OFF_WDT   8448     // [2][64]
#define OFF_BDT2  8576     // [64]
#define OFF_DS2   8640     // [64]
#define OFF_A2    8704     // [64][17]
#define OFF_XF    9792     // [64][33]
#define OFF_XP    11904    // [64][68]
#define OFF_GZ    16256    // [64][68]
#define OFF_YS    20608    // [64][68]
#define OFF_B     24960    // [64][16]
#define OFF_C     25984    // [64][16]
#define OFF_DTSR  27008    // [64][2]
#define OFF_GACC  27136    // [8][4][2]
#define SMEM_FLOATS 27200  // 108800 B -> 2 CTAs/SM

__device__ __forceinline__ float ex2f(float x) {
    float y; asm("ex2.approx.ftz.f32 %0, %1;" : "=f"(y) : "f"(x)); return y;
}
__device__ __forceinline__ float rcpf(float x) {
    float y; asm("rcp.approx.ftz.f32 %0, %1;" : "=f"(y) : "f"(x)); return y;
}
__device__ __forceinline__ ULL pack2(float lo, float hi) {
    ULL d; asm("mov.b64 %0, {%1, %2};" : "=l"(d) : "f"(lo), "f"(hi)); return d;
}
__device__ __forceinline__ ULL dup2(float v) { return pack2(v, v); }
__device__ __forceinline__ void unpack2(ULL v, float& lo, float& hi) {
    asm("mov.b64 {%0, %1}, %2;" : "=f"(lo), "=f"(hi) : "l"(v));
}
__device__ __forceinline__ ULL f2fma(ULL a, ULL b, ULL c) {
    ULL d; asm("fma.rn.f32x2 %0, %1, %2, %3;" : "=l"(d) : "l"(a), "l"(b), "l"(c)); return d;
}
// gelu via A&S 7.1.26 erf approximation (|eps| <= ~2e-7)
__device__ __forceinline__ float fast_gelu(float v) {
    float s = fabsf(v) * 0.70710678118f;
    float t = rcpf(fmaf(0.3275911f, s, 1.0f));
    float e = ex2f(-s * s * LOG2E);
    float p = fmaf(1.061405429f, t, -1.453152027f);
    p = fmaf(p, t, 1.421413741f);
    p = fmaf(p, t, -0.284496736f);
    p = fmaf(p, t, 0.254829592f);
    float erfa = fmaf(-p * t, e, 1.0f);       // erf(|v|/sqrt2)
    float erfv = copysignf(erfa, v);
    return 0.5f * v * (1.0f + erfv);
}

__global__ __launch_bounds__(256, 2) void k1_main(
    const float* __restrict__ x, const float* __restrict__ W_in,
    const float* __restrict__ W_x, const float* __restrict__ W_dt,
    const float* __restrict__ b_dt, const float* __restrict__ A_logs,
    const float* __restrict__ Ds, const float* __restrict__ W_out)
{
    extern __shared__ float S[];
    const int tid = threadIdx.x;
    const int bid = blockIdx.x;

    // ---------------- load weights to smem ----------------
    for (int i = tid; i < 4096; i += 256) S[OFF_WIN + i] = W_in[i];
    for (int i = tid; i < 64 * 34; i += 256) {
        int d = i / 34, j = i - d * 34;
        S[OFF_WX + d * 36 + j] = W_x[i];
    }
    for (int i = tid; i < 2048; i += 256) S[OFF_WOUT + i] = W_out[i];
    if (tid < 128) S[OFF_WDT + tid] = W_dt[tid];
    if (tid < 64) {
        S[OFF_BDT2 + tid] = 2.0f * b_dt[tid];
        S[OFF_DS2 + tid]  = 2.0f * Ds[tid];
    }
    int ok = 1;
    for (int i = tid; i < 1024; i += 256) {
        int d = i >> 4, n = i & 15;
        float ae = __expf(A_logs[i]);
        if (fabsf(ae - (float)(n + 1)) > 1e-3f * (float)(n + 1)) ok = 0;
        S[OFF_A2 + d * 17 + n] = -ae * LOG2E;
    }

    // ---------------- load x tile (vectorized: 1 channel / thread) ----------------
    {
        int m0 = bid * 8;
        int b = m0 >> 12;
        int h = (m0 >> 6) & 63;
        int w0 = m0 & 63;
        const float* xb = x + b * (256 * 4096) + h * 64 + w0;
        int c = tid;                    // channel 0..255
        int t = c >> 5, g = c & 31;
        const float4* src = reinterpret_cast<const float4*>(xb + c * 4096);
        float4 v0 = src[0];
        float4 v1 = src[1];
        S[OFF_XF + (0 * 8 + t) * 33 + g] = v0.x;
        S[OFF_XF + (1 * 8 + t) * 33 + g] = v0.y;
        S[OFF_XF + (2 * 8 + t) * 33 + g] = v0.z;
        S[OFF_XF + (3 * 8 + t) * 33 + g] = v0.w;
        S[OFF_XF + (4 * 8 + t) * 33 + g] = v1.x;
        S[OFF_XF + (5 * 8 + t) * 33 + g] = v1.y;
        S[OFF_XF + (6 * 8 + t) * 33 + g] = v1.z;
        S[OFF_XF + (7 * 8 + t) * 33 + g] = v1.w;
    }
    const int fast = __syncthreads_and(ok);

    // ---- GEMM1 (packed f32x2): [64x32]@[32x128], 4 rows x 8 cols per thread ----
    {
        const int rg  = tid >> 4;   // rows 4rg..4rg+3
        const int cgp = tid & 15;   // cols 8cgp..8cgp+7
        ULL acc[4][4];
        #pragma unroll
        for (int i = 0; i < 4; i++)
            #pragma unroll
            for (int j = 0; j < 4; j++) acc[i][j] = 0ULL;
        #pragma unroll 4
        for (int k = 0; k < 32; k++) {
            const ulonglong2* wp = reinterpret_cast<const ulonglong2*>(&S[OFF_WIN + k * 128 + cgp * 8]);
            ulonglong2 wA = wp[0], wB = wp[1];
            #pragma unroll
            for (int i = 0; i < 4; i++) {
                ULL ap = dup2(S[OFF_XF + (4 * rg + i) * 33 + k]);
                acc[i][0] = f2fma(ap, wA.x, acc[i][0]);
                acc[i][1] = f2fma(ap, wA.y, acc[i][1]);
                acc[i][2] = f2fma(ap, wB.x, acc[i][2]);
                acc[i][3] = f2fma(ap, wB.y, acc[i][3]);
            }
        }
        if (cgp < 8) {
            #pragma unroll
            for (int i = 0; i < 4; i++) {
                ULL* X = reinterpret_cast<ULL*>(&S[OFF_XP + (4 * rg + i) * 68 + cgp * 8]);
                X[0] = acc[i][0]; X[1] = acc[i][1]; X[2] = acc[i][2]; X[3] = acc[i][3];
            }
        } else {
            int c0 = (cgp - 8) * 8;
            #pragma unroll
            for (int i = 0; i < 4; i++) {
                int row = 4 * rg + i;
                #pragma unroll
                for (int j = 0; j < 4; j++) {
                    float lo, hi;
                    unpack2(acc[i][j], lo, hi);
                    S[OFF_GZ + row * 68 + c0 + 2 * j]     = fast_gelu(lo);
                    S[OFF_GZ + row * 68 + c0 + 2 * j + 1] = fast_gelu(hi);
                }
            }
        }
    }
    __syncthreads();

    // ---- GEMM2 (packed): [64x64]@[64x34], 2 rows x 4 cols on ALL 256 threads ----
    {
        const int rp = tid >> 3;   // rows 2rp, 2rp+1
        const int cq = tid & 7;    // cols 4cq..4cq+3
        ULL acc0[2], acc1[2];
        acc0[0] = acc0[1] = acc1[0] = acc1[1] = 0ULL;
        #pragma unroll 4
        for (int k = 0; k < 64; k++) {
            ulonglong2 w = *reinterpret_cast<const ulonglong2*>(&S[OFF_WX + k * 36 + 4 * cq]);
            ULL a0 = dup2(S[OFF_XP + (2 * rp) * 68 + k]);
            ULL a1 = dup2(S[OFF_XP + (2 * rp + 1) * 68 + k]);
            acc0[0] = f2fma(a0, w.x, acc0[0]);
            acc0[1] = f2fma(a0, w.y, acc0[1]);
            acc1[0] = f2fma(a1, w.x, acc1[0]);
            acc1[1] = f2fma(a1, w.y, acc1[1]);
        }
        #pragma unroll
        for (int i = 0; i < 2; i++) {
            int r = 2 * rp + i;
            ULL v0 = i ? acc1[0] : acc0[0];
            ULL v1 = i ? acc1[1] : acc0[1];
            #pragma unroll
            for (int pp = 0; pp < 2; pp++) {
                int c0 = 4 * cq + 2 * pp;
                ULL v = pp ? v1 : v0;
                if (c0 == 0)
                    *reinterpret_cast<ULL*>(&S[OFF_DTSR + r * 2]) = v;
                else if (c0 < 18)
                    *reinterpret_cast<ULL*>(&S[OFF_B + r * 16 + (c0 - 2)]) = v;
                else
                    *reinterpret_cast<ULL*>(&S[OFF_C + r * 16 + (c0 - 18)]) = v;
            }
        }
        // tail cols 32,33 -> C[14],C[15] on warps 6-7
        if (tid >= 192) {
            int r = tid - 192;
            ULL acc = 0ULL;
            #pragma unroll 8
            for (int k = 0; k < 64; k++) {
                ULL w = *reinterpret_cast<const ULL*>(&S[OFF_WX + k * 36 + 32]);
                acc = f2fma(dup2(S[OFF_XP + r * 68 + k]), w, acc);
            }
            *reinterpret_cast<ULL*>(&S[OFF_C + r * 16 + 14]) = acc;
        }
    }
    __syncthreads();

    // ---------------- bidirectional selective scan (scalar, 4-way ILP) --------
    {
        int p  = tid >> 5;
        int d0 = tid & 31;
        float du0[8], du1[8], rr0[8], rr1[8];
        #pragma unroll
        for (int t = 0; t < 8; t++) {
            int r = p * 8 + t;
            float q0 = S[OFF_DTSR + r * 2];
            float q1 = S[OFF_DTSR + r * 2 + 1];
            float v0 = fmaf(q0, S[OFF_WDT + d0],      fmaf(q1, S[OFF_WDT + 64 + d0],      S[OFF_BDT2 + d0]));
            float v1 = fmaf(q0, S[OFF_WDT + d0 + 32], fmaf(q1, S[OFF_WDT + 96 + d0],      S[OFF_BDT2 + d0 + 32]));
            float e0 = __expf(v0), e1 = __expf(v1);
            float s0 = (v0 < -3.0f) ? e0 * (1.0f - e0 * (0.5f - 0.33333334f * e0)) : log1pf(e0);
            float s1 = (v1 < -3.0f) ? e1 * (1.0f - e1 * (0.5f - 0.33333334f * e1)) : log1pf(e1);
            du0[t] = s0 * S[OFF_XP + r * 68 + d0];
            du1[t] = s1 * S[OFF_XP + r * 68 + d0 + 32];
            rr0[t] = fast ? ex2f(-s0 * LOG2E) : s0;
            rr1[t] = fast ? ex2f(-s1 * LOG2E) : s1;
        }
        const float* A2a = &S[OFF_A2 + d0 * 17];
        const float* A2b = &S[OFF_A2 + (d0 + 32) * 17];
        float h0[16], h1[16];
        #pragma unroll
        for (int n = 0; n < 16; n++) { h0[n] = 0.0f; h1[n] = 0.0f; }

        // forward pass
        for (int t = 0; t < 8; t++) {
            int r = p * 8 + t;
            float y0, y1;
            if (fast) {
                float w0 = rr0[t], w1 = rr1[t];
                float w0_2 = w0 * w0,   w1_2 = w1 * w1;
                float w0_4 = w0_2 * w0_2, w1_4 = w1_2 * w1_2;
                float c00 = w0, c01 = w0_2, c02 = w0_2 * w0, c03 = w0_4;
                float c10 = w1, c11 = w1_2, c12 = w1_2 * w1, c13 = w1_4;
                float dd0 = du0[t], dd1 = du1[t];
                float ya0 = 0.0f, ya1 = 0.0f, ya2 = 0.0f, ya3 = 0.0f;
                float yb0 = 0.0f, yb1 = 0.0f, yb2 = 0.0f, yb3 = 0.0f;
                const float4* Bp4 = reinterpret_cast<const float4*>(&S[OFF_B + r * 16]);
                const float4* Cp4 = reinterpret_cast<const float4*>(&S[OFF_C + r * 16]);
                #pragma unroll
                for (int jj = 0; jj < 4; jj++) {
                    float4 Bq = Bp4[jj];
                    float4 Cq = Cp4[jj];
                    int n = 4 * jj;
                    h0[n]   = fmaf(c00, h0[n],   dd0 * Bq.x);  ya0 = fmaf(h0[n],   Cq.x, ya0);
                    h0[n+1] = fmaf(c01, h0[n+1], dd0 * Bq.y);  ya1 = fmaf(h0[n+1], Cq.y, ya1);
                    h0[n+2] = fmaf(c02, h0[n+2], dd0 * Bq.z);  ya2 = fmaf(h0[n+2], Cq.z, ya2);
                    h0[n+3] = fmaf(c03, h0[n+3], dd0 * Bq.w);  ya3 = fmaf(h0[n+3], Cq.w, ya3);
                    h1[n]   = fmaf(c10, h1[n],   dd1 * Bq.x);  yb0 = fmaf(h1[n],   Cq.x, yb0);
                    h1[n+1] = fmaf(c11, h1[n+1], dd1 * Bq.y);  yb1 = fmaf(h1[n+1], Cq.y, yb1);
                    h1[n+2] = fmaf(c12, h1[n+2], dd1 * Bq.z);  yb2 = fmaf(h1[n+2], Cq.z, yb2);
                    h1[n+3] = fmaf(c13, h1[n+3], dd1 * Bq.w);  yb3 = fmaf(h1[n+3], Cq.w, yb3);
                    if (jj < 3) {
                        c00 *= w0_4; c01 *= w0_4; c02 *= w0_4; c03 *= w0_4;
                        c10 *= w1_4; c11 *= w1_4; c12 *= w1_4; c13 *= w1_4;
                    }
                }
                y0 = (ya0 + ya1) + (ya2 + ya3);
                y1 = (yb0 + yb1) + (yb2 + yb3);
            } else {
                float sp0 = rr0[t], sp1 = rr1[t];
                y0 = 0.0f; y1 = 0.0f;
                #pragma unroll
                for (int n = 0; n < 16; n++) {
                    float Bn = S[OFF_B + r * 16 + n];
                    float Cn = S[OFF_C + r * 16 + n];
                    float a0 = ex2f(sp0 * A2a[n]);
                    float a1 = ex2f(sp1 * A2b[n]);
                    h0[n] = fmaf(a0, h0[n], du0[t] * Bn);
                    h1[n] = fmaf(a1, h1[n], du1[t] * Bn);
                    y0 = fmaf(h0[n], Cn, y0);
                    y1 = fmaf(h1[n], Cn, y1);
                }
            }
            float u0 = S[OFF_XP + r * 68 + d0];
            float u1 = S[OFF_XP + r * 68 + d0 + 32];
            S[OFF_YS + r * 68 + d0]      = fmaf(u0, S[OFF_DS2 + d0], y0);
            S[OFF_YS + r * 68 + d0 + 32] = fmaf(u1, S[OFF_DS2 + d0 + 32], y1);
        }

        // backward pass + gate
        #pragma unroll
        for (int n = 0; n < 16; n++) { h0[n] = 0.0f; h1[n] = 0.0f; }
        for (int t = 7; t >= 0; t--) {
            int r = p * 8 + t;
            float y0, y1;
            if (fast) {
                float w0 = rr0[t], w1 = rr1[t];
                float w0_2 = w0 * w0,   w1_2 = w1 * w1;
                float w0_4 = w0_2 * w0_2, w1_4 = w1_2 * w1_2;
                float c00 = w0, c01 = w0_2, c02 = w0_2 * w0, c03 = w0_4;
                float c10 = w1, c11 = w1_2, c12 = w1_2 * w1, c13 = w1_4;
                float dd0 = du0[t], dd1 = du1[t];
                float ya0 = 0.0f, ya1 = 0.0f, ya2 = 0.0f, ya3 = 0.0f;
                float yb0 = 0.0f, yb1 = 0.0f, yb2 = 0.0f, yb3 = 0.0f;
                const float4* Bp4 = reinterpret_cast<const float4*>(&S[OFF_B + r * 16]);
                const float4* Cp4 = reinterpret_cast<const float4*>(&S[OFF_C + r * 16]);
                #pragma unroll
                for (int jj = 0; jj < 4; jj++) {
                    float4 Bq = Bp4[jj];
                    float4 Cq = Cp4[jj];
                    int n = 4 * jj;
                    h0[n]   = fmaf(c00, h0[n],   dd0 * Bq.x);  ya0 = fmaf(h0[n],   Cq.x, ya0);
                    h0[n+1] = fmaf(c01, h0[n+1], dd0 * Bq.y);  ya1 = fmaf(h0[n+1], Cq.y, ya1);
                    h0[n+2] = fmaf(c02, h0[n+2], dd0 * Bq.z);  ya2 = fmaf(h0[n+2], Cq.z, ya2);
                    h0[n+3] = fmaf(c03, h0[n+3], dd0 * Bq.w);  ya3 = fmaf(h0[n+3], Cq.w, ya3);
                    h1[n]   = fmaf(c10, h1[n],   dd1 * Bq.x);  yb0 = fmaf(h1[n],   Cq.x, yb0);
                    h1[n+1] = fmaf(c11, h1[n+1], dd1 * Bq.y);  yb1 = fmaf(h1[n+1], Cq.y, yb1);
                    h1[n+2] = fmaf(c12, h1[n+2], dd1 * Bq.z);  yb2 = fmaf(h1[n+2], Cq.z, yb2);
                    h1[n+3] = fmaf(c13, h1[n+3], dd1 * Bq.w);  yb3 = fmaf(h1[n+3], Cq.w, yb3);
                    if (jj < 3) {
                        c00 *= w0_4; c01 *= w0_4; c02 *= w0_4; c03 *= w0_4;
                        c10 *= w1_4; c11 *= w1_4; c12 *= w1_4; c13 *= w1_4;
                    }
                }
                y0 = (ya0 + ya1) + (ya2 + ya3);
                y1 = (yb0 + yb1) + (yb2 + yb3);
            } else {
                float sp0 = rr0[t], sp1 = rr1[t];
                y0 = 0.0f; y1 = 0.0f;
                #pragma unroll
                for (int n = 0; n < 16; n++) {
                    float Bn = S[OFF_B + r * 16 + n];
                    float Cn = S[OFF_C + r * 16 + n];
                    float a0 = ex2f(sp0 * A2a[n]);
                    float a1 = ex2f(sp1 * A2b[n]);
                    h0[n] = fmaf(a0, h0[n], du0[t] * Bn);
                    h1[n] = fmaf(a1, h1[n], du1[t] * Bn);
                    y0 = fmaf(h0[n], Cn, y0);
                    y1 = fmaf(h1[n], Cn, y1);
                }
            }
            S[OFF_YS + r * 68 + d0]      = (S[OFF_YS + r * 68 + d0]      + y0) * S[OFF_GZ + r * 68 + d0];
            S[OFF_YS + r * 68 + d0 + 32] = (S[OFF_YS + r * 68 + d0 + 32] + y1) * S[OFF_GZ + r * 68 + d0 + 32];
        }
    }
    __syncthreads();

    // ---- GEMM3 (packed): [64x64]@[64x32] -> y_pre + group partials ----
    {
        int rp = tid >> 3;
        int cq = tid & 7;
        ULL acc0[2], acc1[2];
        acc0[0] = acc0[1] = acc1[0] = acc1[1] = 0ULL;
        #pragma unroll 4
        for (int k = 0; k < 64; k++) {
            ulonglong2 w = *reinterpret_cast<const ulonglong2*>(&S[OFF_WOUT + k * 32 + 4 * cq]);
            ULL a0 = dup2(S[OFF_YS + (2 * rp) * 68 + k]);
            ULL a1 = dup2(S[OFF_YS + (2 * rp + 1) * 68 + k]);
            acc0[0] = f2fma(a0, w.x, acc0[0]);
            acc0[1] = f2fma(a0, w.y, acc0[1]);
            acc1[0] = f2fma(a1, w.x, acc1[0]);
            acc1[1] = f2fma(a1, w.y, acc1[1]);
        }
        int m0 = bid * 8;
        float s = 0.0f, ss = 0.0f;
        #pragma unroll
        for (int i = 0; i < 2; i++) {
            int row = 2 * rp + i;
            int p = row >> 3, t = row & 7;
            ULL v0 = i ? acc1[0] : acc0[0];
            ULL v1 = i ? acc1[1] : acc0[1];
            ULL* dst = reinterpret_cast<ULL*>(&g_ypre[(m0 + p) * 256 + t * 32 + 4 * cq]);
            dst[0] = v0; dst[1] = v1;
            float a, b, c, d;
            unpack2(v0, a, b); unpack2(v1, c, d);
            s  += (a + b) + (c + d);
            ss += (a * a + b * b) + (c * c + d * d);
        }
        #pragma unroll
        for (int off = 4; off; off >>= 1) {
            s  += __shfl_down_sync(0xffffffffu, s,  off, 8);
            ss += __shfl_down_sync(0xffffffffu, ss, off, 8);
        }
        if ((tid & 7) == 0) {
            int w = tid >> 5, g = rp & 3;
            S[OFF_GACC + (w * 4 + g) * 2]     = s;
            S[OFF_GACC + (w * 4 + g) * 2 + 1] = ss;
        }
    }
    __syncthreads();
    if (tid < 8) {
        int g = tid & 3, hh = tid >> 2;
        float v = 0.0f;
        #pragma unroll
        for (int w = 0; w < 8; w++) v += S[OFF_GACC + (w * 4 + g) * 2 + hh];
        g_part[bid * 8 + g * 2 + hh] = v;
    }
}

// ---------------- kernel 2: partials -> 16 stats ----------------
__global__ void k2_stats() {
    __shared__ float ssum[256], ssq[256];
    int b = blockIdx.x >> 2, g = blockIdx.x & 3;
    int tid = threadIdx.x;
    float s = 0.0f, q = 0.0f;
    for (int j = tid; j < 512; j += 256) {
        int blk = b * 512 + j;
        s += g_part[blk * 8 + g * 2];
        q += g_part[blk * 8 + g * 2 + 1];
    }
    ssum[tid] = s; ssq[tid] = q;
    __syncthreads();
    for (int st = 128; st; st >>= 1) {
        if (tid < st) { ssum[tid] += ssum[tid + st]; ssq[tid] += ssq[tid + st]; }
        __syncthreads();
    }
    if (tid == 0) {
        float invN = 1.0f / 262144.0f;
        float mean = ssum[0] * invN;
        float var  = ssq[0] * invN - mean * mean;
        g_stats[blockIdx.x * 2]     = mean;
        g_stats[blockIdx.x * 2 + 1] = rsqrtf(var + 1e-5f);
    }
}

// ---------------- kernel 3: groupnorm affine + transpose + residual ----------------
__global__ __launch_bounds__(256) void k3_final(
    const float* __restrict__ x, const float* __restrict__ gn_w,
    const float* __restrict__ gn_b, float* __restrict__ out)
{
    __shared__ float sm[32][33];
    int tx = threadIdx.x, ty = threadIdx.y;
    int ct = blockIdx.x & 7, wt = blockIdx.x >> 3;
    int h = blockIdx.y, b = blockIdx.z;
    int c0 = ct * 32, w0 = wt * 32;
    int c = c0 + tx;
    int grp = c >> 6;
    float mean = g_stats[(b * 4 + grp) * 2];
    float rsig = g_stats[(b * 4 + grp) * 2 + 1];
    float gw = gn_w[c], gb = gn_b[c];
    const float* yp = g_ypre + ((b * 64 + h) * 64 + w0) * 256;
    #pragma unroll
    for (int i = 0; i < 4; i++) {
        int wl = ty + 8 * i;
        float v = yp[wl * 256 + c];
        sm[wl][tx] = fmaf((v - mean) * rsig, gw, gb);
    }
    __syncthreads();
    #pragma unroll
    for (int i = 0; i < 4; i++) {
        int cl = ty + 8 * i;
        int gi = ((b * 256 + c0 + cl) * 64 + h) * 64 + w0 + tx;
        out[gi] = x[gi] + sm[tx][cl];
    }
}

extern "C" void kernel_launch(void* const* d_in, const int* in_sizes, int n_in,
                              void* d_out, int out_size) {
    const float* x      = (const float*)d_in[0];
    const float* W_in   = (const float*)d_in[1];
    const float* W_x    = (const float*)d_in[2];
    const float* W_dt   = (const float*)d_in[3];
    const float* b_dt   = (const float*)d_in[4];
    const float* A_logs = (const float*)d_in[5];
    const float* Ds     = (const float*)d_in[6];
    const float* W_out  = (const float*)d_in[7];
    const float* gn_w   = (const float*)d_in[8];
    const float* gn_b   = (const float*)d_in[9];
    float* out = (float*)d_out;

    cudaFuncSetAttribute(k1_main, cudaFuncAttributeMaxDynamicSharedMemorySize,
                         SMEM_FLOATS * 4);
    k1_main<<<NBLK1, 256, SMEM_FLOATS * 4>>>(x, W_in, W_x, W_dt, b_dt, A_logs, Ds, W_out);
    k2_stats<<<16, 256>>>();
    k3_final<<<dim3(16, 64, 4), dim3(32, 8)>>>(x, gn_w, gn_b, out);
}